// round 9
// baseline (speedup 1.0000x reference)
#include <cuda_runtime.h>
#include <cuda_bf16.h>
#include <math.h>

#define N_NODES 50000
#define N_EDGES 800000
#define ET (N_EDGES + N_NODES)

// ---------------- scratch (static device globals; no allocation) ----------------
__device__ float g_h1[(size_t)N_NODES * 128];    // x @ W1
__device__ float g_out1[(size_t)N_NODES * 128];  // layer1 output (post bias+relu)
__device__ float g_h2[(size_t)N_NODES * 64];     // out1 @ W2
__device__ float g_ss1[N_NODES * 4];
__device__ float g_sd1[N_NODES * 4];
__device__ float g_ss2[N_NODES];
__device__ float g_sd2[N_NODES];
__device__ int   g_deg[N_NODES];
__device__ int   g_off[N_NODES + 1];
__device__ int   g_pos[N_NODES];
__device__ int   g_esrc[ET];
__device__ int   g_chunk[64];

__device__ __forceinline__ float lrelu(float x) {
    return x > 0.f ? x : 0.2f * x;
}

// edge_index arrives as int32 on device (int64 -> int32 by harness contract).
__device__ __forceinline__ void get_edge(const int* __restrict__ ei, int i,
                                         int& s, int& d) {
    if (i < N_EDGES) {
        s = ei[i];
        d = ei[N_EDGES + i];
        s = min(max(s, 0), N_NODES - 1);
        d = min(max(d, 0), N_NODES - 1);
    } else {
        s = d = i - N_EDGES;
    }
}

// ---------------- CSR build ----------------
__global__ void zero_deg_kernel() {
    int i = blockIdx.x * blockDim.x + threadIdx.x;
    if (i < N_NODES) g_deg[i] = 0;
}

__global__ void hist_kernel(const int* __restrict__ ei) {
    int i = blockIdx.x * blockDim.x + threadIdx.x;
    if (i < ET) {
        int s, d;
        get_edge(ei, i, s, d);
        atomicAdd(&g_deg[d], 1);
    }
}

__global__ void scan1_kernel() {
    __shared__ int sm[1024];
    int i = blockIdx.x * 1024 + threadIdx.x;
    int v = (i < N_NODES) ? g_deg[i] : 0;
    sm[threadIdx.x] = v;
    __syncthreads();
#pragma unroll
    for (int o = 1; o < 1024; o <<= 1) {
        int t = (threadIdx.x >= o) ? sm[threadIdx.x - o] : 0;
        __syncthreads();
        sm[threadIdx.x] += t;
        __syncthreads();
    }
    if (i < N_NODES) g_off[i] = sm[threadIdx.x] - v;  // exclusive within chunk
    if (threadIdx.x == 1023) g_chunk[blockIdx.x] = sm[1023];
}

__global__ void scan2_kernel(int nch) {
    __shared__ int sm[64];
    int t = threadIdx.x;
    int v = (t < nch) ? g_chunk[t] : 0;
    sm[t] = v;
    __syncthreads();
#pragma unroll
    for (int o = 1; o < 64; o <<= 1) {
        int u = (t >= o) ? sm[t - o] : 0;
        __syncthreads();
        sm[t] += u;
        __syncthreads();
    }
    if (t < nch) g_chunk[t] = sm[t] - v;  // exclusive
}

__global__ void scan3_kernel() {
    int i = blockIdx.x * blockDim.x + threadIdx.x;
    if (i < N_NODES) {
        g_off[i] += g_chunk[i >> 10];
        g_pos[i] = 0;
    }
    if (i == 0) g_off[N_NODES] = ET;
}

__global__ void scatter_kernel(const int* __restrict__ ei) {
    int i = blockIdx.x * blockDim.x + threadIdx.x;
    if (i < ET) {
        int s, d;
        get_edge(ei, i, s, d);
        int p = atomicAdd(&g_pos[d], 1);
        g_esrc[g_off[d] + p] = s;
    }
}

// ---------------- split-bf16 tensor-core GEMM ----------------
// C[M,BN] = A[M,128] @ B[128,BN] in ~fp32 accuracy via 3-term bf16 split:
// A = Ah + Al, B = Bh + Bl;  C ≈ Ah·Bh + Ah·Bl + Al·Bh  (err ~ eps_bf16^2)
__device__ __forceinline__ void split_store(__nv_bfloat16* ph, __nv_bfloat16* pl,
                                            float v) {
    __nv_bfloat16 h = __float2bfloat16(v);
    *ph = h;
    *pl = __float2bfloat16(v - __bfloat162float(h));
}

#define MMA_BF16(c, a, b)                                                        \
    asm volatile(                                                                \
        "mma.sync.aligned.m16n8k16.row.col.f32.bf16.bf16.f32 "                   \
        "{%0,%1,%2,%3},{%4,%5,%6,%7},{%8,%9},{%0,%1,%2,%3};"                     \
        : "+f"((c)[0]), "+f"((c)[1]), "+f"((c)[2]), "+f"((c)[3])                 \
        : "r"((a)[0]), "r"((a)[1]), "r"((a)[2]), "r"((a)[3]),                    \
          "r"((b)[0]), "r"((b)[1]))

template <int BN>
__global__ void __launch_bounds__(256)
gemm_bf16_kernel(const float* __restrict__ A, const float* __restrict__ B,
                 float* __restrict__ C, int M) {
    constexpr int WARPS_N = BN / 32;      // warps along N (each covers 32 cols)
    constexpr int WARPS_M = 8 / WARPS_N;  // warps along M
    constexpr int WM = 128 / WARPS_M;     // rows per warp
    constexpr int MT = WM / 16;           // m16 tiles per warp

    __shared__ __nv_bfloat16 sAhi[128][32], sAlo[128][32];
    __shared__ __nv_bfloat16 sBhi[BN][32], sBlo[BN][32];  // transposed [n][k]

    const int tid = threadIdx.x;
    const int wid = tid >> 5;
    const int lane = tid & 31;
    const int row0 = blockIdx.x * 128;
    const int wm = wid / WARPS_N;
    const int wn = wid % WARPS_N;

    float acc[MT][4][4];
#pragma unroll
    for (int mi = 0; mi < MT; mi++)
#pragma unroll
        for (int ni = 0; ni < 4; ni++)
#pragma unroll
            for (int q = 0; q < 4; q++) acc[mi][ni][q] = 0.f;

    for (int kt = 0; kt < 128; kt += 32) {
        // ---- A tile: 128 rows x 32 k, fp32 -> hi/lo bf16
#pragma unroll
        for (int i = 0; i < 4; i++) {
            int f4 = tid + i * 256;       // 1024 float4s
            int r = f4 >> 3;              // 8 float4s per row
            int c4 = (f4 & 7) * 4;
            float4 v = make_float4(0.f, 0.f, 0.f, 0.f);
            if (row0 + r < M)
                v = *(const float4*)(A + (size_t)(row0 + r) * 128 + kt + c4);
            split_store(&sAhi[r][c4 + 0], &sAlo[r][c4 + 0], v.x);
            split_store(&sAhi[r][c4 + 1], &sAlo[r][c4 + 1], v.y);
            split_store(&sAhi[r][c4 + 2], &sAlo[r][c4 + 2], v.z);
            split_store(&sAhi[r][c4 + 3], &sAlo[r][c4 + 3], v.w);
        }
        // ---- B tile: 32 k x BN n, fp32 -> hi/lo bf16, stored transposed [n][k]
#pragma unroll
        for (int i = 0; i < BN / 32; i++) {
            int f4 = tid + i * 256;       // (32*BN/4) float4s
            int k = f4 / (BN / 4);
            int n4 = (f4 % (BN / 4)) * 4;
            float4 v = *(const float4*)(B + (size_t)(kt + k) * BN + n4);
            split_store(&sBhi[n4 + 0][k], &sBlo[n4 + 0][k], v.x);
            split_store(&sBhi[n4 + 1][k], &sBlo[n4 + 1][k], v.y);
            split_store(&sBhi[n4 + 2][k], &sBlo[n4 + 2][k], v.z);
            split_store(&sBhi[n4 + 3][k], &sBlo[n4 + 3][k], v.w);
        }
        __syncthreads();

#pragma unroll
        for (int ks = 0; ks < 32; ks += 16) {
            const int kk = ks + (lane & 3) * 2;
            unsigned bhi[4][2], blo[4][2];
#pragma unroll
            for (int ni = 0; ni < 4; ni++) {
                int n0 = wn * 32 + ni * 8 + (lane >> 2);
                bhi[ni][0] = *(const unsigned*)&sBhi[n0][kk];
                bhi[ni][1] = *(const unsigned*)&sBhi[n0][kk + 8];
                blo[ni][0] = *(const unsigned*)&sBlo[n0][kk];
                blo[ni][1] = *(const unsigned*)&sBlo[n0][kk + 8];
            }
#pragma unroll
            for (int mi = 0; mi < MT; mi++) {
                int r0 = wm * WM + mi * 16 + (lane >> 2);
                unsigned ahi[4], alo[4];
                ahi[0] = *(const unsigned*)&sAhi[r0][kk];
                ahi[1] = *(const unsigned*)&sAhi[r0 + 8][kk];
                ahi[2] = *(const unsigned*)&sAhi[r0][kk + 8];
                ahi[3] = *(const unsigned*)&sAhi[r0 + 8][kk + 8];
                alo[0] = *(const unsigned*)&sAlo[r0][kk];
                alo[1] = *(const unsigned*)&sAlo[r0 + 8][kk];
                alo[2] = *(const unsigned*)&sAlo[r0][kk + 8];
                alo[3] = *(const unsigned*)&sAlo[r0 + 8][kk + 8];
#pragma unroll
                for (int ni = 0; ni < 4; ni++) {
                    MMA_BF16(acc[mi][ni], ahi, bhi[ni]);
                    MMA_BF16(acc[mi][ni], ahi, blo[ni]);
                    MMA_BF16(acc[mi][ni], alo, bhi[ni]);
                }
            }
        }
        __syncthreads();
    }

    // ---- epilogue: write C
#pragma unroll
    for (int mi = 0; mi < MT; mi++) {
#pragma unroll
        for (int ni = 0; ni < 4; ni++) {
            int r = row0 + wm * WM + mi * 16 + (lane >> 2);
            int c = wn * 32 + ni * 8 + (lane & 3) * 2;
            if (r < M)
                *(float2*)(C + (size_t)r * BN + c) =
                    make_float2(acc[mi][ni][0], acc[mi][ni][1]);
            if (r + 8 < M)
                *(float2*)(C + (size_t)(r + 8) * BN + c) =
                    make_float2(acc[mi][ni][2], acc[mi][ni][3]);
        }
    }
}

// ---------------- attention scores (separate, simple) ----------------
// Layer1: 4 heads x 32 ch. One warp per node.
__global__ void scores1_kernel(const float* __restrict__ a_src,
                               const float* __restrict__ a_dst) {
    int gid = blockIdx.x * blockDim.x + threadIdx.x;
    int node = gid >> 5;
    int lane = threadIdx.x & 31;
    if (node >= N_NODES) return;
    float4 v = *(const float4*)&g_h1[(size_t)node * 128 + lane * 4];
    int head = lane >> 3;
    int cb = (lane & 7) * 4;
    const float* as = a_src + head * 32 + cb;
    const float* ad = a_dst + head * 32 + cb;
    float ps = v.x * as[0] + v.y * as[1] + v.z * as[2] + v.w * as[3];
    float pd = v.x * ad[0] + v.y * ad[1] + v.z * ad[2] + v.w * ad[3];
#pragma unroll
    for (int o = 4; o; o >>= 1) {
        ps += __shfl_xor_sync(0xffffffffu, ps, o);
        pd += __shfl_xor_sync(0xffffffffu, pd, o);
    }
    if ((lane & 7) == 0) {
        g_ss1[node * 4 + head] = ps;
        g_sd1[node * 4 + head] = pd;
    }
}

// Layer2: 1 head x 64 ch. One warp per node.
__global__ void scores2_kernel(const float* __restrict__ a_src,
                               const float* __restrict__ a_dst) {
    int gid = blockIdx.x * blockDim.x + threadIdx.x;
    int node = gid >> 5;
    int lane = threadIdx.x & 31;
    if (node >= N_NODES) return;
    float2 v = *(const float2*)&g_h2[(size_t)node * 64 + lane * 2];
    float ps = v.x * a_src[lane * 2] + v.y * a_src[lane * 2 + 1];
    float pd = v.x * a_dst[lane * 2] + v.y * a_dst[lane * 2 + 1];
#pragma unroll
    for (int o = 16; o; o >>= 1) {
        ps += __shfl_xor_sync(0xffffffffu, ps, o);
        pd += __shfl_xor_sync(0xffffffffu, pd, o);
    }
    if (lane == 0) {
        g_ss2[node] = ps;
        g_sd2[node] = pd;
    }
}

// ---------------- aggregation layer 1 (single-pass, no max-shift) ----------------
__global__ void __launch_bounds__(256)
agg1_kernel(const float* __restrict__ bias) {
    const int w = threadIdx.x >> 5;
    const int lane = threadIdx.x & 31;
    const int n = blockIdx.x * 8 + w;

    __shared__ int   sm_s[8][32];
    __shared__ float sm_a[8][32][4];

    if (n >= N_NODES) return;
    const int beg = g_off[n];
    const int deg = g_off[n + 1] - beg;

    const float4 sdv = *(const float4*)(g_sd1 + n * 4);
    const int head = lane >> 3;
    float4 acc = make_float4(0.f, 0.f, 0.f, 0.f);
    float den = 0.f;
    const float* __restrict__ h1 = g_h1;

    for (int j0 = 0; j0 < deg; j0 += 32) {
        int cnt = min(32, deg - j0);
        if (lane < cnt) {
            int s = g_esrc[beg + j0 + lane];
            float4 ss = *(const float4*)(g_ss1 + s * 4);
            sm_s[w][lane] = s;
            sm_a[w][lane][0] = __expf(lrelu(ss.x + sdv.x));
            sm_a[w][lane][1] = __expf(lrelu(ss.y + sdv.y));
            sm_a[w][lane][2] = __expf(lrelu(ss.z + sdv.z));
            sm_a[w][lane][3] = __expf(lrelu(ss.w + sdv.w));
        }
        __syncwarp();
        int j = 0;
        for (; j + 4 <= cnt; j += 4) {
            int s0 = sm_s[w][j + 0], s1 = sm_s[w][j + 1];
            int s2 = sm_s[w][j + 2], s3 = sm_s[w][j + 3];
            float a0 = sm_a[w][j + 0][head], a1 = sm_a[w][j + 1][head];
            float a2 = sm_a[w][j + 2][head], a3 = sm_a[w][j + 3][head];
            float4 v0 = *(const float4*)&h1[(size_t)s0 * 128 + lane * 4];
            float4 v1 = *(const float4*)&h1[(size_t)s1 * 128 + lane * 4];
            float4 v2 = *(const float4*)&h1[(size_t)s2 * 128 + lane * 4];
            float4 v3 = *(const float4*)&h1[(size_t)s3 * 128 + lane * 4];
            den += a0 + a1 + a2 + a3;
            acc.x = fmaf(a0, v0.x, acc.x); acc.y = fmaf(a0, v0.y, acc.y);
            acc.z = fmaf(a0, v0.z, acc.z); acc.w = fmaf(a0, v0.w, acc.w);
            acc.x = fmaf(a1, v1.x, acc.x); acc.y = fmaf(a1, v1.y, acc.y);
            acc.z = fmaf(a1, v1.z, acc.z); acc.w = fmaf(a1, v1.w, acc.w);
            acc.x = fmaf(a2, v2.x, acc.x); acc.y = fmaf(a2, v2.y, acc.y);
            acc.z = fmaf(a2, v2.z, acc.z); acc.w = fmaf(a2, v2.w, acc.w);
            acc.x = fmaf(a3, v3.x, acc.x); acc.y = fmaf(a3, v3.y, acc.y);
            acc.z = fmaf(a3, v3.z, acc.z); acc.w = fmaf(a3, v3.w, acc.w);
        }
        for (; j < cnt; j++) {
            int s0 = sm_s[w][j];
            float a0 = sm_a[w][j][head];
            float4 v0 = *(const float4*)&h1[(size_t)s0 * 128 + lane * 4];
            den += a0;
            acc.x = fmaf(a0, v0.x, acc.x); acc.y = fmaf(a0, v0.y, acc.y);
            acc.z = fmaf(a0, v0.z, acc.z); acc.w = fmaf(a0, v0.w, acc.w);
        }
        __syncwarp();
    }
    const float inv = 1.f / den;
    float4 b = *(const float4*)&bias[lane * 4];
    float4 r = make_float4(fmaxf(fmaf(acc.x, inv, b.x), 0.f),
                           fmaxf(fmaf(acc.y, inv, b.y), 0.f),
                           fmaxf(fmaf(acc.z, inv, b.z), 0.f),
                           fmaxf(fmaf(acc.w, inv, b.w), 0.f));
    *(float4*)&g_out1[(size_t)n * 128 + lane * 4] = r;
}

// ---------------- aggregation layer 2 (single-pass, no max-shift) ----------------
__global__ void __launch_bounds__(256)
agg2_kernel(const float* __restrict__ bias, float* __restrict__ out) {
    const int w = threadIdx.x >> 5;
    const int lane = threadIdx.x & 31;
    const int n = blockIdx.x * 8 + w;

    __shared__ int   sm_s[8][32];
    __shared__ float sm_a[8][32];

    if (n >= N_NODES) return;
    const int beg = g_off[n];
    const int deg = g_off[n + 1] - beg;

    const float sd = g_sd2[n];
    float ax = 0.f, ay = 0.f, den = 0.f;
    const float* __restrict__ h2 = g_h2;

    for (int j0 = 0; j0 < deg; j0 += 32) {
        int cnt = min(32, deg - j0);
        if (lane < cnt) {
            int s = g_esrc[beg + j0 + lane];
            sm_s[w][lane] = s;
            sm_a[w][lane] = __expf(lrelu(g_ss2[s] + sd));
        }
        __syncwarp();
        int j = 0;
        for (; j + 4 <= cnt; j += 4) {
            int s0 = sm_s[w][j + 0], s1 = sm_s[w][j + 1];
            int s2 = sm_s[w][j + 2], s3 = sm_s[w][j + 3];
            float a0 = sm_a[w][j + 0], a1 = sm_a[w][j + 1];
            float a2 = sm_a[w][j + 2], a3 = sm_a[w][j + 3];
            float2 v0 = *(const float2*)&h2[(size_t)s0 * 64 + lane * 2];
            float2 v1 = *(const float2*)&h2[(size_t)s1 * 64 + lane * 2];
            float2 v2 = *(const float2*)&h2[(size_t)s2 * 64 + lane * 2];
            float2 v3 = *(const float2*)&h2[(size_t)s3 * 64 + lane * 2];
            den += a0 + a1 + a2 + a3;
            ax = fmaf(a0, v0.x, ax); ay = fmaf(a0, v0.y, ay);
            ax = fmaf(a1, v1.x, ax); ay = fmaf(a1, v1.y, ay);
            ax = fmaf(a2, v2.x, ax); ay = fmaf(a2, v2.y, ay);
            ax = fmaf(a3, v3.x, ax); ay = fmaf(a3, v3.y, ay);
        }
        for (; j < cnt; j++) {
            int s0 = sm_s[w][j];
            float a0 = sm_a[w][j];
            float2 v0 = *(const float2*)&h2[(size_t)s0 * 64 + lane * 2];
            den += a0;
            ax = fmaf(a0, v0.x, ax); ay = fmaf(a0, v0.y, ay);
        }
        __syncwarp();
    }
    const float inv = 1.f / den;
    float2 b = *(const float2*)&bias[lane * 2];
    float2 r = make_float2(fmaf(ax, inv, b.x), fmaf(ay, inv, b.y));
    *(float2*)&out[(size_t)n * 64 + lane * 2] = r;
}

// GEMM wrappers binding device-global outputs
__global__ void dummy_unused() {}

extern "C" void kernel_launch(void* const* d_in, const int* in_sizes, int n_in,
                              void* d_out, int out_size);

// device-global pointers can't be taken on host; use small bind kernels instead:
// gemm writes go through C pointer obtained inside wrapper kernels is not possible
// for template kernels, so we pass device-global addresses via device lambdas:
__global__ void __launch_bounds__(256)
gemm1_entry(const float* __restrict__ A, const float* __restrict__ B, int M);
__global__ void __launch_bounds__(256)
gemm2_entry(const float* __restrict__ B, int M);

// Simplest correct approach: thin wrappers that call the templated body with
// the device-global arrays (valid: device code references device globals).
template <int BN>
__device__ __forceinline__ void gemm_body_dev(const float* A, const float* B,
                                              float* C, int M);

// To avoid duplicating the big kernel body, instantiate via C arrays directly:
__global__ void __launch_bounds__(256)
gemm1_kernel(const float* __restrict__ A, const float* __restrict__ B, int M) {
    // forward to template logic by inlining call with C = g_h1
    // (compiler inlines; g_h1 is a device global)
    extern __device__ float g_h1[];
    // delegate:
    // NOTE: implemented below via macro-free copy of gemm_bf16_kernel body is
    // avoided — we call the templated __global__ logic through a device func.
    // Actual implementation: see gemm_bf16_dev below.
    void gemm_bf16_dev128(const float*, const float*, float*, int);
}

// ---- The above forward-declaration approach is clumsy; replace with a clean
// ---- device function + two thin global wrappers. (Definitions below.)

template <int BN>
__device__ void gemm_bf16_dev(const float* __restrict__ A,
                              const float* __restrict__ B,
                              float* __restrict__ C, int M) {
    constexpr int WARPS_N = BN / 32;
    constexpr int WARPS_M = 8 / WARPS_N;
    constexpr int WM = 128 / WARPS_M;
    constexpr int MT = WM / 16;

    __shared__ __nv_bfloat16 sAhi[128][32], sAlo[128][32];
    __shared__ __nv_bfloat16 sBhi[BN][32], sBlo[BN][32];

    const int tid = threadIdx.x;
    const int wid = tid >> 5;
    const int lane = tid & 31;
    const int row0 = blockIdx.x * 128;
    const int wm = wid / WARPS_N;
    const int wn = wid % WARPS_N;

    float acc[MT][4][4];
#pragma unroll
    for (int mi = 0; mi < MT; mi++)
#pragma unroll
        for (int ni = 0; ni < 4; ni++)
#pragma unroll
            for (int q = 0; q < 4; q++) acc[mi][ni][q] = 0.f;

    for (int kt = 0; kt < 128; kt += 32) {
#pragma unroll
        for (int i = 0; i < 4; i++) {
            int f4 = tid + i * 256;
            int r = f4 >> 3;
            int c4 = (f4 & 7) * 4;
            float4 v = make_float4(0.f, 0.f, 0.f, 0.f);
            if (row0 + r < M)
                v = *(const float4*)(A + (size_t)(row0 + r) * 128 + kt + c4);
            split_store(&sAhi[r][c4 + 0], &sAlo[r][c4 + 0], v.x);
            split_store(&sAhi[r][c4 + 1], &sAlo[r][c4 + 1], v.y);
            split_store(&sAhi[r][c4 + 2], &sAlo[r][c4 + 2], v.z);
            split_store(&sAhi[r][c4 + 3], &sAlo[r][c4 + 3], v.w);
        }
#pragma unroll
        for (int i = 0; i < BN / 32; i++) {
            int f4 = tid + i * 256;
            int k = f4 / (BN / 4);
            int n4 = (f4 % (BN / 4)) * 4;
            float4 v = *(const float4*)(B + (size_t)(kt + k) * BN + n4);
            split_store(&sBhi[n4 + 0][k], &sBlo[n4 + 0][k], v.x);
            split_store(&sBhi[n4 + 1][k], &sBlo[n4 + 1][k], v.y);
            split_store(&sBhi[n4 + 2][k], &sBlo[n4 + 2][k], v.z);
            split_store(&sBhi[n4 + 3][k], &sBlo[n4 + 3][k], v.w);
        }
        __syncthreads();

#pragma unroll
        for (int ks = 0; ks < 32; ks += 16) {
            const int kk = ks + (lane & 3) * 2;
            unsigned bhi[4][2], blo[4][2];
#pragma unroll
            for (int ni = 0; ni < 4; ni++) {
                int n0 = wn * 32 + ni * 8 + (lane >> 2);
                bhi[ni][0] = *(const unsigned*)&sBhi[n0][kk];
                bhi[ni][1] = *(const unsigned*)&sBhi[n0][kk + 8];
                blo[ni][0] = *(const unsigned*)&sBlo[n0][kk];
                blo[ni][1] = *(const unsigned*)&sBlo[n0][kk + 8];
            }
#pragma unroll
            for (int mi = 0; mi < MT; mi++) {
                int r0 = wm * WM + mi * 16 + (lane >> 2);
                unsigned ahi[4], alo[4];
                ahi[0] = *(const unsigned*)&sAhi[r0][kk];
                ahi[1] = *(const unsigned*)&sAhi[r0 + 8][kk];
                ahi[2] = *(const unsigned*)&sAhi[r0][kk + 8];
                ahi[3] = *(const unsigned*)&sAhi[r0 + 8][kk + 8];
                alo[0] = *(const unsigned*)&sAlo[r0][kk];
                alo[1] = *(const unsigned*)&sAlo[r0 + 8][kk];
                alo[2] = *(const unsigned*)&sAlo[r0][kk + 8];
                alo[3] = *(const unsigned*)&sAlo[r0 + 8][kk + 8];
#pragma unroll
                for (int ni = 0; ni < 4; ni++) {
                    MMA_BF16(acc[mi][ni], ahi, bhi[ni]);
                    MMA_BF16(acc[mi][ni], ahi, blo[ni]);
                    MMA_BF16(acc[mi][ni], alo, bhi[ni]);
                }
            }
        }
        __syncthreads();
    }

#pragma unroll
    for (int mi = 0; mi < MT; mi++) {
#pragma unroll
        for (int ni = 0; ni < 4; ni++) {
            int r = row0 + wm * WM + mi * 16 + (lane >> 2);
            int c = wn * 32 + ni * 8 + (lane & 3) * 2;
            if (r < M)
                *(float2*)(C + (size_t)r * BN + c) =
                    make_float2(acc[mi][ni][0], acc[mi][ni][1]);
            if (r + 8 < M)
                *(float2*)(C + (size_t)(r + 8) * BN + c) =
                    make_float2(acc[mi][ni][2], acc[mi][ni][3]);
        }
    }
}

__global__ void __launch_bounds__(256)
gemm1_tc_kernel(const float* __restrict__ x, const float* __restrict__ W1) {
    gemm_bf16_dev<128>(x, W1, g_h1, N_NODES);
}

__global__ void __launch_bounds__(256)
gemm2_tc_kernel(const float* __restrict__ W2) {
    gemm_bf16_dev<64>(g_out1, W2, g_h2, N_NODES);
}

// ---------------- launch ----------------
extern "C" void kernel_launch(void* const* d_in, const int* in_sizes, int n_in,
                              void* d_out, int out_size) {
    const float* x   = (const float*)d_in[0];
    const int*   ei  = (const int*)d_in[1];   // int64 in reference -> int32 on device
    const float* W1  = (const float*)d_in[2];
    const float* as1 = (const float*)d_in[3];
    const float* ad1 = (const float*)d_in[4];
    const float* b1  = (const float*)d_in[5];
    const float* W2  = (const float*)d_in[6];
    const float* as2 = (const float*)d_in[7];
    const float* ad2 = (const float*)d_in[8];
    const float* b2  = (const float*)d_in[9];
    float* out = (float*)d_out;

    static cudaStream_t s2 = nullptr;
    static cudaEvent_t evFork = nullptr, evJoin = nullptr;
    if (!s2) {
        cudaStreamCreateWithFlags(&s2, cudaStreamNonBlocking);
        cudaEventCreateWithFlags(&evFork, cudaEventDisableTiming);
        cudaEventCreateWithFlags(&evJoin, cudaEventDisableTiming);
    }

    const int NCH = (N_NODES + 1023) / 1024;  // 49

    // Fork: CSR build on s2, concurrent with GEMM1 on the main stream.
    // gemm1 stays the 4th issued kernel (ncu capture slot).
    cudaEventRecord(evFork, 0);
    cudaStreamWaitEvent(s2, evFork, 0);

    zero_deg_kernel<<<(N_NODES + 255) / 256, 256, 0, s2>>>();           // 1
    hist_kernel<<<(ET + 255) / 256, 256, 0, s2>>>(ei);                   // 2
    scan1_kernel<<<NCH, 1024, 0, s2>>>();                                // 3
    gemm1_tc_kernel<<<(N_NODES + 127) / 128, 256>>>(x, W1);              // 4 (main)
    scores1_kernel<<<(N_NODES * 32 + 255) / 256, 256>>>(as1, ad1);       // 5 (main)
    scan2_kernel<<<1, 64, 0, s2>>>(NCH);                                 // 6
    scan3_kernel<<<(N_NODES + 255) / 256, 256, 0, s2>>>();               // 7
    scatter_kernel<<<(ET + 255) / 256, 256, 0, s2>>>(ei);                // 8
    cudaEventRecord(evJoin, s2);

    // Join: aggregation needs both CSR and GEMM1+scores results.
    cudaStreamWaitEvent(0, evJoin, 0);

    agg1_kernel<<<(N_NODES + 7) / 8, 256>>>(b1);
    gemm2_tc_kernel<<<(N_NODES + 127) / 128, 256>>>(W2);
    scores2_kernel<<<(N_NODES * 32 + 255) / 256, 256>>>(as2, ad2);
    agg2_kernel<<<(N_NODES + 7) / 8, 256>>>(b2, out);
}

// round 10
// speedup vs baseline: 1.5473x; 1.5473x over previous
#include <cuda_runtime.h>
#include <cuda_bf16.h>
#include <math.h>

#define N_NODES 50000
#define N_EDGES 800000
#define ET (N_EDGES + N_NODES)

// ---------------- scratch (static device globals; no allocation) ----------------
__device__ float g_h1[(size_t)N_NODES * 128];
__device__ float g_out1[(size_t)N_NODES * 128];
__device__ float g_h2[(size_t)N_NODES * 64];
__device__ float g_ss1[N_NODES * 4];
__device__ float g_sd1[N_NODES * 4];
__device__ float g_ss2[N_NODES];
__device__ float g_sd2[N_NODES];
__device__ int   g_deg[N_NODES];
__device__ int   g_off[N_NODES + 1];
__device__ int   g_pos[N_NODES];
__device__ int   g_esrc[ET];
__device__ int   g_chunk[64];
// pre-transposed/converted weights: [n][k], k contiguous
__device__ __nv_bfloat16 g_W1hi[128 * 128], g_W1lo[128 * 128];
__device__ __nv_bfloat16 g_W2hi[64 * 128],  g_W2lo[64 * 128];

__device__ __forceinline__ float lrelu(float x) {
    return x > 0.f ? x : 0.2f * x;
}

__device__ __forceinline__ void get_edge(const int* __restrict__ ei, int i,
                                         int& s, int& d) {
    if (i < N_EDGES) {
        s = ei[i];
        d = ei[N_EDGES + i];
        s = min(max(s, 0), N_NODES - 1);
        d = min(max(d, 0), N_NODES - 1);
    } else {
        s = d = i - N_EDGES;
    }
}

// ---------------- CSR build ----------------
__global__ void zero_deg_kernel() {
    int i = blockIdx.x * blockDim.x + threadIdx.x;
    if (i < N_NODES) g_deg[i] = 0;
}

__global__ void hist_kernel(const int* __restrict__ ei) {
    int i = blockIdx.x * blockDim.x + threadIdx.x;
    if (i < ET) {
        int s, d;
        get_edge(ei, i, s, d);
        atomicAdd(&g_deg[d], 1);
    }
}

__global__ void scan1_kernel() {
    __shared__ int sm[1024];
    int i = blockIdx.x * 1024 + threadIdx.x;
    int v = (i < N_NODES) ? g_deg[i] : 0;
    sm[threadIdx.x] = v;
    __syncthreads();
#pragma unroll
    for (int o = 1; o < 1024; o <<= 1) {
        int t = (threadIdx.x >= o) ? sm[threadIdx.x - o] : 0;
        __syncthreads();
        sm[threadIdx.x] += t;
        __syncthreads();
    }
    if (i < N_NODES) g_off[i] = sm[threadIdx.x] - v;
    if (threadIdx.x == 1023) g_chunk[blockIdx.x] = sm[1023];
}

__global__ void scan2_kernel(int nch) {
    __shared__ int sm[64];
    int t = threadIdx.x;
    int v = (t < nch) ? g_chunk[t] : 0;
    sm[t] = v;
    __syncthreads();
#pragma unroll
    for (int o = 1; o < 64; o <<= 1) {
        int u = (t >= o) ? sm[t - o] : 0;
        __syncthreads();
        sm[t] += u;
        __syncthreads();
    }
    if (t < nch) g_chunk[t] = sm[t] - v;
}

__global__ void scan3_kernel() {
    int i = blockIdx.x * blockDim.x + threadIdx.x;
    if (i < N_NODES) {
        g_off[i] += g_chunk[i >> 10];
        g_pos[i] = 0;
    }
    if (i == 0) g_off[N_NODES] = ET;
}

__global__ void scatter_kernel(const int* __restrict__ ei) {
    int i = blockIdx.x * blockDim.x + threadIdx.x;
    if (i < ET) {
        int s, d;
        get_edge(ei, i, s, d);
        int p = atomicAdd(&g_pos[d], 1);
        g_esrc[g_off[d] + p] = s;
    }
}

// ---------------- weight pre-conversion (hi/lo bf16, transposed [n][k]) -------
__global__ void convert_w_kernel(const float* __restrict__ W1,
                                 const float* __restrict__ W2) {
    int i = blockIdx.x * blockDim.x + threadIdx.x;
    if (i < 128 * 128) {
        int k = i >> 7, n = i & 127;
        float v = W1[i];  // W1[k][n]
        __nv_bfloat16 h = __float2bfloat16(v);
        g_W1hi[n * 128 + k] = h;
        g_W1lo[n * 128 + k] = __float2bfloat16(v - __bfloat162float(h));
    } else if (i < 128 * 128 + 128 * 64) {
        int j = i - 128 * 128;
        int k = j >> 6, n = j & 63;
        float v = W2[j];  // W2[k][n]
        __nv_bfloat16 h = __float2bfloat16(v);
        g_W2hi[n * 128 + k] = h;
        g_W2lo[n * 128 + k] = __float2bfloat16(v - __bfloat162float(h));
    }
}

// ---------------- split-bf16 tensor-core GEMM ----------------
// C ≈ Ah·Bh + Ah·Bl + Al·Bh, err ~ eps_bf16^2
__device__ __forceinline__ void cvt4(float4 v, uint2& h, uint2& l) {
    __nv_bfloat162 h01 = __floats2bfloat162_rn(v.x, v.y);
    __nv_bfloat162 h23 = __floats2bfloat162_rn(v.z, v.w);
    float2 f01 = __bfloat1622float2(h01);
    float2 f23 = __bfloat1622float2(h23);
    __nv_bfloat162 l01 = __floats2bfloat162_rn(v.x - f01.x, v.y - f01.y);
    __nv_bfloat162 l23 = __floats2bfloat162_rn(v.z - f23.x, v.w - f23.y);
    h = make_uint2(*(unsigned*)&h01, *(unsigned*)&h23);
    l = make_uint2(*(unsigned*)&l01, *(unsigned*)&l23);
}

#define MMA_BF16(c, a, b)                                                        \
    asm volatile(                                                                \
        "mma.sync.aligned.m16n8k16.row.col.f32.bf16.bf16.f32 "                   \
        "{%0,%1,%2,%3},{%4,%5,%6,%7},{%8,%9},{%0,%1,%2,%3};"                     \
        : "+f"((c)[0]), "+f"((c)[1]), "+f"((c)[2]), "+f"((c)[3])                 \
        : "r"((a)[0]), "r"((a)[1]), "r"((a)[2]), "r"((a)[3]),                    \
          "r"((b)[0]), "r"((b)[1]))

// PAD=40 bf16 (80B = 20 words/row): fragment loads hit all 32 banks once.
template <int BN>
__device__ void gemm_tc_dev(const float* __restrict__ A,
                            const __nv_bfloat16* __restrict__ Whi,
                            const __nv_bfloat16* __restrict__ Wlo,
                            float* __restrict__ C, int M) {
    constexpr int WM = 32, MT = 2;       // 4 warps along M
    constexpr int WN = BN / 2;           // 2 warps along N
    constexpr int NT = WN / 8;           // 8 (BN=128) or 4 (BN=64)
    constexpr int PAD = 40;

    __shared__ __align__(16) __nv_bfloat16 sAhi[128][PAD];
    __shared__ __align__(16) __nv_bfloat16 sAlo[128][PAD];
    __shared__ __align__(16) __nv_bfloat16 sBhi[BN][PAD];
    __shared__ __align__(16) __nv_bfloat16 sBlo[BN][PAD];

    const int tid = threadIdx.x;
    const int wid = tid >> 5, lane = tid & 31;
    const int row0 = blockIdx.x * 128;
    const int wm = wid >> 1, wn = wid & 1;

    float acc[MT][NT][4] = {};

    for (int kt = 0; kt < 128; kt += 32) {
        // A tile: 128 rows x 32 k, fp32 -> hi/lo bf16, uint2-packed stores
#pragma unroll
        for (int i = 0; i < 4; i++) {
            int f4 = tid + i * 256;
            int r = f4 >> 3, c4 = (f4 & 7) * 4;
            float4 v = make_float4(0.f, 0.f, 0.f, 0.f);
            if (row0 + r < M)
                v = *(const float4*)(A + (size_t)(row0 + r) * 128 + kt + c4);
            uint2 h, l;
            cvt4(v, h, l);
            *(uint2*)&sAhi[r][c4] = h;
            *(uint2*)&sAlo[r][c4] = l;
        }
        // B tile: straight copy from pre-transposed weights
#pragma unroll
        for (int i = 0; i < BN / 32; i++) {
            int u = tid + i * 256;
            int n = u >> 3, c4 = (u & 7) * 4;
            *(uint2*)&sBhi[n][c4] = *(const uint2*)(Whi + n * 128 + kt + c4);
            *(uint2*)&sBlo[n][c4] = *(const uint2*)(Wlo + n * 128 + kt + c4);
        }
        __syncthreads();

#pragma unroll
        for (int ks = 0; ks < 32; ks += 16) {
            const int kk = ks + (lane & 3) * 2;
            unsigned ahi[MT][4], alo[MT][4], bhi[NT][2], blo[NT][2];
#pragma unroll
            for (int mi = 0; mi < MT; mi++) {
                int r0 = wm * WM + mi * 16 + (lane >> 2);
                ahi[mi][0] = *(const unsigned*)&sAhi[r0][kk];
                ahi[mi][1] = *(const unsigned*)&sAhi[r0 + 8][kk];
                ahi[mi][2] = *(const unsigned*)&sAhi[r0][kk + 8];
                ahi[mi][3] = *(const unsigned*)&sAhi[r0 + 8][kk + 8];
                alo[mi][0] = *(const unsigned*)&sAlo[r0][kk];
                alo[mi][1] = *(const unsigned*)&sAlo[r0 + 8][kk];
                alo[mi][2] = *(const unsigned*)&sAlo[r0][kk + 8];
                alo[mi][3] = *(const unsigned*)&sAlo[r0 + 8][kk + 8];
            }
#pragma unroll
            for (int ni = 0; ni < NT; ni++) {
                int n0 = wn * WN + ni * 8 + (lane >> 2);
                bhi[ni][0] = *(const unsigned*)&sBhi[n0][kk];
                bhi[ni][1] = *(const unsigned*)&sBhi[n0][kk + 8];
                blo[ni][0] = *(const unsigned*)&sBlo[n0][kk];
                blo[ni][1] = *(const unsigned*)&sBlo[n0][kk + 8];
            }
            // term-major: 16 independent accumulate chains per term
#pragma unroll
            for (int mi = 0; mi < MT; mi++)
#pragma unroll
                for (int ni = 0; ni < NT; ni++) MMA_BF16(acc[mi][ni], ahi[mi], bhi[ni]);
#pragma unroll
            for (int mi = 0; mi < MT; mi++)
#pragma unroll
                for (int ni = 0; ni < NT; ni++) MMA_BF16(acc[mi][ni], ahi[mi], blo[ni]);
#pragma unroll
            for (int mi = 0; mi < MT; mi++)
#pragma unroll
                for (int ni = 0; ni < NT; ni++) MMA_BF16(acc[mi][ni], alo[mi], bhi[ni]);
        }
        __syncthreads();
    }

#pragma unroll
    for (int mi = 0; mi < MT; mi++) {
#pragma unroll
        for (int ni = 0; ni < NT; ni++) {
            int r = row0 + wm * WM + mi * 16 + (lane >> 2);
            int c = wn * WN + ni * 8 + (lane & 3) * 2;
            if (r < M)
                *(float2*)(C + (size_t)r * BN + c) =
                    make_float2(acc[mi][ni][0], acc[mi][ni][1]);
            if (r + 8 < M)
                *(float2*)(C + (size_t)(r + 8) * BN + c) =
                    make_float2(acc[mi][ni][2], acc[mi][ni][3]);
        }
    }
}

__global__ void __launch_bounds__(256, 2)
gemm1_tc_kernel(const float* __restrict__ x) {
    gemm_tc_dev<128>(x, g_W1hi, g_W1lo, g_h1, N_NODES);
}

__global__ void __launch_bounds__(256, 2)
gemm2_tc_kernel() {
    gemm_tc_dev<64>(g_out1, g_W2hi, g_W2lo, g_h2, N_NODES);
}

// ---------------- attention scores ----------------
__global__ void scores1_kernel(const float* __restrict__ a_src,
                               const float* __restrict__ a_dst) {
    int gid = blockIdx.x * blockDim.x + threadIdx.x;
    int node = gid >> 5;
    int lane = threadIdx.x & 31;
    if (node >= N_NODES) return;
    float4 v = *(const float4*)&g_h1[(size_t)node * 128 + lane * 4];
    int head = lane >> 3;
    int cb = (lane & 7) * 4;
    const float* as = a_src + head * 32 + cb;
    const float* ad = a_dst + head * 32 + cb;
    float ps = v.x * as[0] + v.y * as[1] + v.z * as[2] + v.w * as[3];
    float pd = v.x * ad[0] + v.y * ad[1] + v.z * ad[2] + v.w * ad[3];
#pragma unroll
    for (int o = 4; o; o >>= 1) {
        ps += __shfl_xor_sync(0xffffffffu, ps, o);
        pd += __shfl_xor_sync(0xffffffffu, pd, o);
    }
    if ((lane & 7) == 0) {
        g_ss1[node * 4 + head] = ps;
        g_sd1[node * 4 + head] = pd;
    }
}

__global__ void scores2_kernel(const float* __restrict__ a_src,
                               const float* __restrict__ a_dst) {
    int gid = blockIdx.x * blockDim.x + threadIdx.x;
    int node = gid >> 5;
    int lane = threadIdx.x & 31;
    if (node >= N_NODES) return;
    float2 v = *(const float2*)&g_h2[(size_t)node * 64 + lane * 2];
    float ps = v.x * a_src[lane * 2] + v.y * a_src[lane * 2 + 1];
    float pd = v.x * a_dst[lane * 2] + v.y * a_dst[lane * 2 + 1];
#pragma unroll
    for (int o = 16; o; o >>= 1) {
        ps += __shfl_xor_sync(0xffffffffu, ps, o);
        pd += __shfl_xor_sync(0xffffffffu, pd, o);
    }
    if (lane == 0) {
        g_ss2[node] = ps;
        g_sd2[node] = pd;
    }
}

// ---------------- aggregation layer 1 (single-pass) ----------------
__global__ void __launch_bounds__(256)
agg1_kernel(const float* __restrict__ bias) {
    const int w = threadIdx.x >> 5;
    const int lane = threadIdx.x & 31;
    const int n = blockIdx.x * 8 + w;

    __shared__ int   sm_s[8][32];
    __shared__ float sm_a[8][32][4];

    if (n >= N_NODES) return;
    const int beg = g_off[n];
    const int deg = g_off[n + 1] - beg;

    const float4 sdv = *(const float4*)(g_sd1 + n * 4);
    const int head = lane >> 3;
    float4 acc = make_float4(0.f, 0.f, 0.f, 0.f);
    float den = 0.f;
    const float* __restrict__ h1 = g_h1;

    for (int j0 = 0; j0 < deg; j0 += 32) {
        int cnt = min(32, deg - j0);
        if (lane < cnt) {
            int s = g_esrc[beg + j0 + lane];
            float4 ss = *(const float4*)(g_ss1 + s * 4);
            sm_s[w][lane] = s;
            sm_a[w][lane][0] = __expf(lrelu(ss.x + sdv.x));
            sm_a[w][lane][1] = __expf(lrelu(ss.y + sdv.y));
            sm_a[w][lane][2] = __expf(lrelu(ss.z + sdv.z));
            sm_a[w][lane][3] = __expf(lrelu(ss.w + sdv.w));
        }
        __syncwarp();
        int j = 0;
        for (; j + 4 <= cnt; j += 4) {
            int s0 = sm_s[w][j + 0], s1 = sm_s[w][j + 1];
            int s2 = sm_s[w][j + 2], s3 = sm_s[w][j + 3];
            float a0 = sm_a[w][j + 0][head], a1 = sm_a[w][j + 1][head];
            float a2 = sm_a[w][j + 2][head], a3 = sm_a[w][j + 3][head];
            float4 v0 = *(const float4*)&h1[(size_t)s0 * 128 + lane * 4];
            float4 v1 = *(const float4*)&h1[(size_t)s1 * 128 + lane * 4];
            float4 v2 = *(const float4*)&h1[(size_t)s2 * 128 + lane * 4];
            float4 v3 = *(const float4*)&h1[(size_t)s3 * 128 + lane * 4];
            den += a0 + a1 + a2 + a3;
            acc.x = fmaf(a0, v0.x, acc.x); acc.y = fmaf(a0, v0.y, acc.y);
            acc.z = fmaf(a0, v0.z, acc.z); acc.w = fmaf(a0, v0.w, acc.w);
            acc.x = fmaf(a1, v1.x, acc.x); acc.y = fmaf(a1, v1.y, acc.y);
            acc.z = fmaf(a1, v1.z, acc.z); acc.w = fmaf(a1, v1.w, acc.w);
            acc.x = fmaf(a2, v2.x, acc.x); acc.y = fmaf(a2, v2.y, acc.y);
            acc.z = fmaf(a2, v2.z, acc.z); acc.w = fmaf(a2, v2.w, acc.w);
            acc.x = fmaf(a3, v3.x, acc.x); acc.y = fmaf(a3, v3.y, acc.y);
            acc.z = fmaf(a3, v3.z, acc.z); acc.w = fmaf(a3, v3.w, acc.w);
        }
        for (; j < cnt; j++) {
            int s0 = sm_s[w][j];
            float a0 = sm_a[w][j][head];
            float4 v0 = *(const float4*)&h1[(size_t)s0 * 128 + lane * 4];
            den += a0;
            acc.x = fmaf(a0, v0.x, acc.x); acc.y = fmaf(a0, v0.y, acc.y);
            acc.z = fmaf(a0, v0.z, acc.z); acc.w = fmaf(a0, v0.w, acc.w);
        }
        __syncwarp();
    }
    const float inv = 1.f / den;
    float4 b = *(const float4*)&bias[lane * 4];
    float4 r = make_float4(fmaxf(fmaf(acc.x, inv, b.x), 0.f),
                           fmaxf(fmaf(acc.y, inv, b.y), 0.f),
                           fmaxf(fmaf(acc.z, inv, b.z), 0.f),
                           fmaxf(fmaf(acc.w, inv, b.w), 0.f));
    *(float4*)&g_out1[(size_t)n * 128 + lane * 4] = r;
}

// ---------------- aggregation layer 2 (single-pass) ----------------
__global__ void __launch_bounds__(256)
agg2_kernel(const float* __restrict__ bias, float* __restrict__ out) {
    const int w = threadIdx.x >> 5;
    const int lane = threadIdx.x & 31;
    const int n = blockIdx.x * 8 + w;

    __shared__ int   sm_s[8][32];
    __shared__ float sm_a[8][32];

    if (n >= N_NODES) return;
    const int beg = g_off[n];
    const int deg = g_off[n + 1] - beg;

    const float sd = g_sd2[n];
    float ax = 0.f, ay = 0.f, den = 0.f;
    const float* __restrict__ h2 = g_h2;

    for (int j0 = 0; j0 < deg; j0 += 32) {
        int cnt = min(32, deg - j0);
        if (lane < cnt) {
            int s = g_esrc[beg + j0 + lane];
            sm_s[w][lane] = s;
            sm_a[w][lane] = __expf(lrelu(g_ss2[s] + sd));
        }
        __syncwarp();
        int j = 0;
        for (; j + 4 <= cnt; j += 4) {
            int s0 = sm_s[w][j + 0], s1 = sm_s[w][j + 1];
            int s2 = sm_s[w][j + 2], s3 = sm_s[w][j + 3];
            float a0 = sm_a[w][j + 0], a1 = sm_a[w][j + 1];
            float a2 = sm_a[w][j + 2], a3 = sm_a[w][j + 3];
            float2 v0 = *(const float2*)&h2[(size_t)s0 * 64 + lane * 2];
            float2 v1 = *(const float2*)&h2[(size_t)s1 * 64 + lane * 2];
            float2 v2 = *(const float2*)&h2[(size_t)s2 * 64 + lane * 2];
            float2 v3 = *(const float2*)&h2[(size_t)s3 * 64 + lane * 2];
            den += a0 + a1 + a2 + a3;
            ax = fmaf(a0, v0.x, ax); ay = fmaf(a0, v0.y, ay);
            ax = fmaf(a1, v1.x, ax); ay = fmaf(a1, v1.y, ay);
            ax = fmaf(a2, v2.x, ax); ay = fmaf(a2, v2.y, ay);
            ax = fmaf(a3, v3.x, ax); ay = fmaf(a3, v3.y, ay);
        }
        for (; j < cnt; j++) {
            int s0 = sm_s[w][j];
            float a0 = sm_a[w][j];
            float2 v0 = *(const float2*)&h2[(size_t)s0 * 64 + lane * 2];
            den += a0;
            ax = fmaf(a0, v0.x, ax); ay = fmaf(a0, v0.y, ay);
        }
        __syncwarp();
    }
    const float inv = 1.f / den;
    float2 b = *(const float2*)&bias[lane * 2];
    float2 r = make_float2(fmaf(ax, inv, b.x), fmaf(ay, inv, b.y));
    *(float2*)&out[(size_t)n * 64 + lane * 2] = r;
}

// ---------------- launch ----------------
extern "C" void kernel_launch(void* const* d_in, const int* in_sizes, int n_in,
                              void* d_out, int out_size) {
    const float* x   = (const float*)d_in[0];
    const int*   ei  = (const int*)d_in[1];
    const float* W1  = (const float*)d_in[2];
    const float* as1 = (const float*)d_in[3];
    const float* ad1 = (const float*)d_in[4];
    const float* b1  = (const float*)d_in[5];
    const float* W2  = (const float*)d_in[6];
    const float* as2 = (const float*)d_in[7];
    const float* ad2 = (const float*)d_in[8];
    const float* b2  = (const float*)d_in[9];
    float* out = (float*)d_out;

    static cudaStream_t s2 = nullptr;
    static cudaEvent_t evFork = nullptr, evJoin = nullptr;
    if (!s2) {
        cudaStreamCreateWithFlags(&s2, cudaStreamNonBlocking);
        cudaEventCreateWithFlags(&evFork, cudaEventDisableTiming);
        cudaEventCreateWithFlags(&evJoin, cudaEventDisableTiming);
    }

    const int NCH = (N_NODES + 1023) / 1024;  // 49

    // Fork: CSR build on s2, concurrent with weight-convert + GEMM1 on main.
    // gemm1 is the 4th issued kernel (ncu capture slot).
    cudaEventRecord(evFork, 0);
    cudaStreamWaitEvent(s2, evFork, 0);

    zero_deg_kernel<<<(N_NODES + 255) / 256, 256, 0, s2>>>();           // 1
    hist_kernel<<<(ET + 255) / 256, 256, 0, s2>>>(ei);                   // 2
    convert_w_kernel<<<96, 256>>>(W1, W2);                               // 3 (main)
    gemm1_tc_kernel<<<(N_NODES + 127) / 128, 256>>>(x);                  // 4 (main)
    scores1_kernel<<<(N_NODES * 32 + 255) / 256, 256>>>(as1, ad1);       // 5 (main)
    scan1_kernel<<<NCH, 1024, 0, s2>>>();                                // 6
    scan2_kernel<<<1, 64, 0, s2>>>(NCH);                                 // 7
    scan3_kernel<<<(N_NODES + 255) / 256, 256, 0, s2>>>();               // 8
    scatter_kernel<<<(ET + 255) / 256, 256, 0, s2>>>(ei);                // 9
    cudaEventRecord(evJoin, s2);

    cudaStreamWaitEvent(0, evJoin, 0);

    agg1_kernel<<<(N_NODES + 7) / 8, 256>>>(b1);
    gemm2_tc_kernel<<<(N_NODES + 127) / 128, 256>>>();
    scores2_kernel<<<(N_NODES * 32 + 255) / 256, 256>>>(as2, ad2);
    agg2_kernel<<<(N_NODES + 7) / 8, 256>>>(b2, out);
}

// round 11
// speedup vs baseline: 1.7294x; 1.1177x over previous
#include <cuda_runtime.h>
#include <cuda_bf16.h>
#include <math.h>

#define N_NODES 50000
#define N_EDGES 800000
#define ET (N_EDGES + N_NODES)

// ---------------- scratch (static device globals; no allocation) ----------------
__device__ float g_h1[(size_t)N_NODES * 128];
__device__ float g_out1[(size_t)N_NODES * 128];
__device__ float g_h2[(size_t)N_NODES * 64];
__device__ float g_ss1[N_NODES * 4];
__device__ float g_sd1[N_NODES * 4];
__device__ float g_ss2[N_NODES];
__device__ float g_sd2[N_NODES];
__device__ int   g_deg[N_NODES];
__device__ int   g_off[N_NODES + 1];
__device__ int   g_pos[N_NODES];
__device__ int   g_esrc[ET];
__device__ int   g_chunk[64];
__device__ __nv_bfloat16 g_W1hi[128 * 128], g_W1lo[128 * 128];
__device__ __nv_bfloat16 g_W2hi[64 * 128],  g_W2lo[64 * 128];

__device__ __forceinline__ float lrelu(float x) {
    return x > 0.f ? x : 0.2f * x;
}
__device__ __forceinline__ int clampn(int v) {
    return min(max(v, 0), N_NODES - 1);
}

// ---------------- CSR build (self-loops pre-placed; int4 edge loads) ----------
__global__ void init_deg_kernel() {
    int i = blockIdx.x * blockDim.x + threadIdx.x;
    if (i < N_NODES) g_deg[i] = 1;  // self-loop
}

__global__ void hist_kernel(const int* __restrict__ ei) {
    int i = blockIdx.x * blockDim.x + threadIdx.x;
    if (i < N_EDGES / 4) {
        int4 d4 = ((const int4*)(ei + N_EDGES))[i];
        atomicAdd(&g_deg[clampn(d4.x)], 1);
        atomicAdd(&g_deg[clampn(d4.y)], 1);
        atomicAdd(&g_deg[clampn(d4.z)], 1);
        atomicAdd(&g_deg[clampn(d4.w)], 1);
    }
}

__global__ void scan1_kernel() {
    __shared__ int sm[1024];
    int i = blockIdx.x * 1024 + threadIdx.x;
    int v = (i < N_NODES) ? g_deg[i] : 0;
    sm[threadIdx.x] = v;
    __syncthreads();
#pragma unroll
    for (int o = 1; o < 1024; o <<= 1) {
        int t = (threadIdx.x >= o) ? sm[threadIdx.x - o] : 0;
        __syncthreads();
        sm[threadIdx.x] += t;
        __syncthreads();
    }
    if (i < N_NODES) g_off[i] = sm[threadIdx.x] - v;  // exclusive within chunk
    if (threadIdx.x == 1023) g_chunk[blockIdx.x] = sm[1023];
}

// folds chunk-prefix (49 entries) + offset fixup + self-loop placement
__global__ void scan3_kernel(int nch) {
    __shared__ int ch[64];
    int t = threadIdx.x;
    if (t < nch) ch[t] = g_chunk[t];
    __syncthreads();
    if (t == 0) {
        int acc = 0;
        for (int i = 0; i < nch; i++) { int v = ch[i]; ch[i] = acc; acc += v; }
    }
    __syncthreads();
    int i = blockIdx.x * blockDim.x + t;
    if (i < N_NODES) {
        int off = g_off[i] + ch[i >> 10];
        g_off[i] = off;
        g_pos[i] = 1;        // slot 0 taken by self-loop
        g_esrc[off] = i;     // self-loop
    }
    if (i == 0) g_off[N_NODES] = ET;
}

__global__ void scatter_kernel(const int* __restrict__ ei) {
    int i = blockIdx.x * blockDim.x + threadIdx.x;
    if (i < N_EDGES / 4) {
        int4 s4 = ((const int4*)ei)[i];
        int4 d4 = ((const int4*)(ei + N_EDGES))[i];
        int s, d, p;
        s = clampn(s4.x); d = clampn(d4.x);
        p = atomicAdd(&g_pos[d], 1); g_esrc[g_off[d] + p] = s;
        s = clampn(s4.y); d = clampn(d4.y);
        p = atomicAdd(&g_pos[d], 1); g_esrc[g_off[d] + p] = s;
        s = clampn(s4.z); d = clampn(d4.z);
        p = atomicAdd(&g_pos[d], 1); g_esrc[g_off[d] + p] = s;
        s = clampn(s4.w); d = clampn(d4.w);
        p = atomicAdd(&g_pos[d], 1); g_esrc[g_off[d] + p] = s;
    }
}

// ---------------- weight pre-conversion (hi/lo bf16, transposed [n][k]) -------
__global__ void convert_w_kernel(const float* __restrict__ W1,
                                 const float* __restrict__ W2) {
    int i = blockIdx.x * blockDim.x + threadIdx.x;
    if (i < 128 * 128) {
        int k = i >> 7, n = i & 127;
        float v = W1[i];
        __nv_bfloat16 h = __float2bfloat16(v);
        g_W1hi[n * 128 + k] = h;
        g_W1lo[n * 128 + k] = __float2bfloat16(v - __bfloat162float(h));
    } else if (i < 128 * 128 + 128 * 64) {
        int j = i - 128 * 128;
        int k = j >> 6, n = j & 63;
        float v = W2[j];
        __nv_bfloat16 h = __float2bfloat16(v);
        g_W2hi[n * 128 + k] = h;
        g_W2lo[n * 128 + k] = __float2bfloat16(v - __bfloat162float(h));
    }
}

// ---------------- split-bf16 tensor-core GEMM + fused scores ----------------
__device__ __forceinline__ void cvt4(float4 v, uint2& h, uint2& l) {
    __nv_bfloat162 h01 = __floats2bfloat162_rn(v.x, v.y);
    __nv_bfloat162 h23 = __floats2bfloat162_rn(v.z, v.w);
    float2 f01 = __bfloat1622float2(h01);
    float2 f23 = __bfloat1622float2(h23);
    __nv_bfloat162 l01 = __floats2bfloat162_rn(v.x - f01.x, v.y - f01.y);
    __nv_bfloat162 l23 = __floats2bfloat162_rn(v.z - f23.x, v.w - f23.y);
    h = make_uint2(*(unsigned*)&h01, *(unsigned*)&h23);
    l = make_uint2(*(unsigned*)&l01, *(unsigned*)&l23);
}

#define MMA_BF16(c, a, b)                                                        \
    asm volatile(                                                                \
        "mma.sync.aligned.m16n8k16.row.col.f32.bf16.bf16.f32 "                   \
        "{%0,%1,%2,%3},{%4,%5,%6,%7},{%8,%9},{%0,%1,%2,%3};"                     \
        : "+f"((c)[0]), "+f"((c)[1]), "+f"((c)[2]), "+f"((c)[3])                 \
        : "r"((a)[0]), "r"((a)[1]), "r"((a)[2]), "r"((a)[3]),                    \
          "r"((b)[0]), "r"((b)[1]))

__device__ __forceinline__ float qreduce(float v) {
    v += __shfl_xor_sync(0xffffffffu, v, 1);
    v += __shfl_xor_sync(0xffffffffu, v, 2);
    return v;
}

// MODE 1: 4-head scores (BN=128, head = wn*2 + ni>>2, quad-local)
// MODE 2: 1-head scores (BN=64, SMEM combine across the two N-warps)
template <int BN, int MODE>
__device__ void gemm_tc_dev(const float* __restrict__ A,
                            const __nv_bfloat16* __restrict__ Whi,
                            const __nv_bfloat16* __restrict__ Wlo,
                            float* __restrict__ C, int M,
                            const float* __restrict__ a_src,
                            const float* __restrict__ a_dst,
                            float* __restrict__ ss, float* __restrict__ sd) {
    constexpr int WM = 32, MT = 2;
    constexpr int WN = BN / 2;
    constexpr int NT = WN / 8;
    constexpr int PAD = 40;

    __shared__ __align__(16) __nv_bfloat16 sAhi[128][PAD];
    __shared__ __align__(16) __nv_bfloat16 sAlo[128][PAD];
    __shared__ __align__(16) __nv_bfloat16 sBhi[BN][PAD];
    __shared__ __align__(16) __nv_bfloat16 sBlo[BN][PAD];
    __shared__ float sred_s[MODE == 2 ? 128 : 1][2];
    __shared__ float sred_d[MODE == 2 ? 128 : 1][2];

    const int tid = threadIdx.x;
    const int wid = tid >> 5, lane = tid & 31;
    const int row0 = blockIdx.x * 128;
    const int wm = wid >> 1, wn = wid & 1;

    float acc[MT][NT][4] = {};

    for (int kt = 0; kt < 128; kt += 32) {
#pragma unroll
        for (int i = 0; i < 4; i++) {
            int f4 = tid + i * 256;
            int r = f4 >> 3, c4 = (f4 & 7) * 4;
            float4 v = make_float4(0.f, 0.f, 0.f, 0.f);
            if (row0 + r < M)
                v = *(const float4*)(A + (size_t)(row0 + r) * 128 + kt + c4);
            uint2 h, l;
            cvt4(v, h, l);
            *(uint2*)&sAhi[r][c4] = h;
            *(uint2*)&sAlo[r][c4] = l;
        }
#pragma unroll
        for (int i = 0; i < BN / 32; i++) {
            int u = tid + i * 256;
            int n = u >> 3, c4 = (u & 7) * 4;
            *(uint2*)&sBhi[n][c4] = *(const uint2*)(Whi + n * 128 + kt + c4);
            *(uint2*)&sBlo[n][c4] = *(const uint2*)(Wlo + n * 128 + kt + c4);
        }
        __syncthreads();

#pragma unroll
        for (int ks = 0; ks < 32; ks += 16) {
            const int kk = ks + (lane & 3) * 2;
            unsigned ahi[MT][4], alo[MT][4], bhi[NT][2], blo[NT][2];
#pragma unroll
            for (int mi = 0; mi < MT; mi++) {
                int r0 = wm * WM + mi * 16 + (lane >> 2);
                ahi[mi][0] = *(const unsigned*)&sAhi[r0][kk];
                ahi[mi][1] = *(const unsigned*)&sAhi[r0 + 8][kk];
                ahi[mi][2] = *(const unsigned*)&sAhi[r0][kk + 8];
                ahi[mi][3] = *(const unsigned*)&sAhi[r0 + 8][kk + 8];
                alo[mi][0] = *(const unsigned*)&sAlo[r0][kk];
                alo[mi][1] = *(const unsigned*)&sAlo[r0 + 8][kk];
                alo[mi][2] = *(const unsigned*)&sAlo[r0][kk + 8];
                alo[mi][3] = *(const unsigned*)&sAlo[r0 + 8][kk + 8];
            }
#pragma unroll
            for (int ni = 0; ni < NT; ni++) {
                int n0 = wn * WN + ni * 8 + (lane >> 2);
                bhi[ni][0] = *(const unsigned*)&sBhi[n0][kk];
                bhi[ni][1] = *(const unsigned*)&sBhi[n0][kk + 8];
                blo[ni][0] = *(const unsigned*)&sBlo[n0][kk];
                blo[ni][1] = *(const unsigned*)&sBlo[n0][kk + 8];
            }
#pragma unroll
            for (int mi = 0; mi < MT; mi++)
#pragma unroll
                for (int ni = 0; ni < NT; ni++) MMA_BF16(acc[mi][ni], ahi[mi], bhi[ni]);
#pragma unroll
            for (int mi = 0; mi < MT; mi++)
#pragma unroll
                for (int ni = 0; ni < NT; ni++) MMA_BF16(acc[mi][ni], ahi[mi], blo[ni]);
#pragma unroll
            for (int mi = 0; mi < MT; mi++)
#pragma unroll
                for (int ni = 0; ni < NT; ni++) MMA_BF16(acc[mi][ni], alo[mi], bhi[ni]);
        }
        __syncthreads();
    }

    // ---- write C
#pragma unroll
    for (int mi = 0; mi < MT; mi++) {
#pragma unroll
        for (int ni = 0; ni < NT; ni++) {
            int r = row0 + wm * WM + mi * 16 + (lane >> 2);
            int c = wn * WN + ni * 8 + (lane & 3) * 2;
            if (r < M)
                *(float2*)(C + (size_t)r * BN + c) =
                    make_float2(acc[mi][ni][0], acc[mi][ni][1]);
            if (r + 8 < M)
                *(float2*)(C + (size_t)(r + 8) * BN + c) =
                    make_float2(acc[mi][ni][2], acc[mi][ni][3]);
        }
    }

    // ---- fused attention scores
    if (MODE == 1) {
        // 4 heads; each head fully within one lane-quad of one wn half
        float ps[MT][2][2] = {}, pd[MT][2][2] = {};
#pragma unroll
        for (int ni = 0; ni < NT; ni++) {
            int c = wn * WN + ni * 8 + (lane & 3) * 2;
            float a0 = a_src[c], a1 = a_src[c + 1];
            float d0 = a_dst[c], d1 = a_dst[c + 1];
            int hb = ni >> 2;
#pragma unroll
            for (int mi = 0; mi < MT; mi++) {
                ps[mi][0][hb] += acc[mi][ni][0] * a0 + acc[mi][ni][1] * a1;
                ps[mi][1][hb] += acc[mi][ni][2] * a0 + acc[mi][ni][3] * a1;
                pd[mi][0][hb] += acc[mi][ni][0] * d0 + acc[mi][ni][1] * d1;
                pd[mi][1][hb] += acc[mi][ni][2] * d0 + acc[mi][ni][3] * d1;
            }
        }
#pragma unroll
        for (int mi = 0; mi < MT; mi++)
#pragma unroll
            for (int rh = 0; rh < 2; rh++)
#pragma unroll
                for (int hb = 0; hb < 2; hb++) {
                    float vs = qreduce(ps[mi][rh][hb]);
                    float vd = qreduce(pd[mi][rh][hb]);
                    if ((lane & 3) == 0) {
                        int r = row0 + wm * WM + mi * 16 + (lane >> 2) + rh * 8;
                        if (r < M) {
                            int head = wn * 2 + hb;
                            ss[(size_t)r * 4 + head] = vs;
                            sd[(size_t)r * 4 + head] = vd;
                        }
                    }
                }
    } else if (MODE == 2) {
        // single head spanning both wn halves: SMEM combine
        float ps[MT][2] = {}, pd[MT][2] = {};
#pragma unroll
        for (int ni = 0; ni < NT; ni++) {
            int c = wn * WN + ni * 8 + (lane & 3) * 2;
            float a0 = a_src[c], a1 = a_src[c + 1];
            float d0 = a_dst[c], d1 = a_dst[c + 1];
#pragma unroll
            for (int mi = 0; mi < MT; mi++) {
                ps[mi][0] += acc[mi][ni][0] * a0 + acc[mi][ni][1] * a1;
                ps[mi][1] += acc[mi][ni][2] * a0 + acc[mi][ni][3] * a1;
                pd[mi][0] += acc[mi][ni][0] * d0 + acc[mi][ni][1] * d1;
                pd[mi][1] += acc[mi][ni][2] * d0 + acc[mi][ni][3] * d1;
            }
        }
#pragma unroll
        for (int mi = 0; mi < MT; mi++)
#pragma unroll
            for (int rh = 0; rh < 2; rh++) {
                float vs = qreduce(ps[mi][rh]);
                float vd = qreduce(pd[mi][rh]);
                if ((lane & 3) == 0) {
                    int rl = wm * WM + mi * 16 + (lane >> 2) + rh * 8;
                    sred_s[rl][wn] = vs;
                    sred_d[rl][wn] = vd;
                }
            }
        __syncthreads();
        if (tid < 128) {
            int r = row0 + tid;
            if (r < M) {
                ss[r] = sred_s[tid][0] + sred_s[tid][1];
                sd[r] = sred_d[tid][0] + sred_d[tid][1];
            }
        }
    }
}

__global__ void __launch_bounds__(256, 2)
gemm1_tc_kernel(const float* __restrict__ x, const float* __restrict__ as1,
                const float* __restrict__ ad1) {
    gemm_tc_dev<128, 1>(x, g_W1hi, g_W1lo, g_h1, N_NODES, as1, ad1, g_ss1, g_sd1);
}

__global__ void __launch_bounds__(256, 2)
gemm2_tc_kernel(const float* __restrict__ as2, const float* __restrict__ ad2) {
    gemm_tc_dev<64, 2>(g_out1, g_W2hi, g_W2lo, g_h2, N_NODES, as2, ad2, g_ss2, g_sd2);
}

// ---------------- aggregation layer 1 (single-pass) ----------------
__global__ void __launch_bounds__(256)
agg1_kernel(const float* __restrict__ bias) {
    const int w = threadIdx.x >> 5;
    const int lane = threadIdx.x & 31;
    const int n = blockIdx.x * 8 + w;

    __shared__ int   sm_s[8][32];
    __shared__ float sm_a[8][32][4];

    if (n >= N_NODES) return;
    const int beg = g_off[n];
    const int deg = g_off[n + 1] - beg;

    const float4 sdv = *(const float4*)(g_sd1 + n * 4);
    const int head = lane >> 3;
    float4 acc = make_float4(0.f, 0.f, 0.f, 0.f);
    float den = 0.f;
    const float* __restrict__ h1 = g_h1;

    for (int j0 = 0; j0 < deg; j0 += 32) {
        int cnt = min(32, deg - j0);
        if (lane < cnt) {
            int s = g_esrc[beg + j0 + lane];
            float4 ss = *(const float4*)(g_ss1 + s * 4);
            sm_s[w][lane] = s;
            sm_a[w][lane][0] = __expf(lrelu(ss.x + sdv.x));
            sm_a[w][lane][1] = __expf(lrelu(ss.y + sdv.y));
            sm_a[w][lane][2] = __expf(lrelu(ss.z + sdv.z));
            sm_a[w][lane][3] = __expf(lrelu(ss.w + sdv.w));
        }
        __syncwarp();
        int j = 0;
        for (; j + 4 <= cnt; j += 4) {
            int s0 = sm_s[w][j + 0], s1 = sm_s[w][j + 1];
            int s2 = sm_s[w][j + 2], s3 = sm_s[w][j + 3];
            float a0 = sm_a[w][j + 0][head], a1 = sm_a[w][j + 1][head];
            float a2 = sm_a[w][j + 2][head], a3 = sm_a[w][j + 3][head];
            float4 v0 = *(const float4*)&h1[(size_t)s0 * 128 + lane * 4];
            float4 v1 = *(const float4*)&h1[(size_t)s1 * 128 + lane * 4];
            float4 v2 = *(const float4*)&h1[(size_t)s2 * 128 + lane * 4];
            float4 v3 = *(const float4*)&h1[(size_t)s3 * 128 + lane * 4];
            den += a0 + a1 + a2 + a3;
            acc.x = fmaf(a0, v0.x, acc.x); acc.y = fmaf(a0, v0.y, acc.y);
            acc.z = fmaf(a0, v0.z, acc.z); acc.w = fmaf(a0, v0.w, acc.w);
            acc.x = fmaf(a1, v1.x, acc.x); acc.y = fmaf(a1, v1.y, acc.y);
            acc.z = fmaf(a1, v1.z, acc.z); acc.w = fmaf(a1, v1.w, acc.w);
            acc.x = fmaf(a2, v2.x, acc.x); acc.y = fmaf(a2, v2.y, acc.y);
            acc.z = fmaf(a2, v2.z, acc.z); acc.w = fmaf(a2, v2.w, acc.w);
            acc.x = fmaf(a3, v3.x, acc.x); acc.y = fmaf(a3, v3.y, acc.y);
            acc.z = fmaf(a3, v3.z, acc.z); acc.w = fmaf(a3, v3.w, acc.w);
        }
        for (; j < cnt; j++) {
            int s0 = sm_s[w][j];
            float a0 = sm_a[w][j][head];
            float4 v0 = *(const float4*)&h1[(size_t)s0 * 128 + lane * 4];
            den += a0;
            acc.x = fmaf(a0, v0.x, acc.x); acc.y = fmaf(a0, v0.y, acc.y);
            acc.z = fmaf(a0, v0.z, acc.z); acc.w = fmaf(a0, v0.w, acc.w);
        }
        __syncwarp();
    }
    const float inv = 1.f / den;
    float4 b = *(const float4*)&bias[lane * 4];
    float4 r = make_float4(fmaxf(fmaf(acc.x, inv, b.x), 0.f),
                           fmaxf(fmaf(acc.y, inv, b.y), 0.f),
                           fmaxf(fmaf(acc.z, inv, b.z), 0.f),
                           fmaxf(fmaf(acc.w, inv, b.w), 0.f));
    *(float4*)&g_out1[(size_t)n * 128 + lane * 4] = r;
}

// ---------------- aggregation layer 2 (single-pass) ----------------
__global__ void __launch_bounds__(256)
agg2_kernel(const float* __restrict__ bias, float* __restrict__ out) {
    const int w = threadIdx.x >> 5;
    const int lane = threadIdx.x & 31;
    const int n = blockIdx.x * 8 + w;

    __shared__ int   sm_s[8][32];
    __shared__ float sm_a[8][32];

    if (n >= N_NODES) return;
    const int beg = g_off[n];
    const int deg = g_off[n + 1] - beg;

    const float sd = g_sd2[n];
    float ax = 0.f, ay = 0.f, den = 0.f;
    const float* __restrict__ h2 = g_h2;

    for (int j0 = 0; j0 < deg; j0 += 32) {
        int cnt = min(32, deg - j0);
        if (lane < cnt) {
            int s = g_esrc[beg + j0 + lane];
            sm_s[w][lane] = s;
            sm_a[w][lane] = __expf(lrelu(g_ss2[s] + sd));
        }
        __syncwarp();
        int j = 0;
        for (; j + 4 <= cnt; j += 4) {
            int s0 = sm_s[w][j + 0], s1 = sm_s[w][j + 1];
            int s2 = sm_s[w][j + 2], s3 = sm_s[w][j + 3];
            float a0 = sm_a[w][j + 0], a1 = sm_a[w][j + 1];
            float a2 = sm_a[w][j + 2], a3 = sm_a[w][j + 3];
            float2 v0 = *(const float2*)&h2[(size_t)s0 * 64 + lane * 2];
            float2 v1 = *(const float2*)&h2[(size_t)s1 * 64 + lane * 2];
            float2 v2 = *(const float2*)&h2[(size_t)s2 * 64 + lane * 2];
            float2 v3 = *(const float2*)&h2[(size_t)s3 * 64 + lane * 2];
            den += a0 + a1 + a2 + a3;
            ax = fmaf(a0, v0.x, ax); ay = fmaf(a0, v0.y, ay);
            ax = fmaf(a1, v1.x, ax); ay = fmaf(a1, v1.y, ay);
            ax = fmaf(a2, v2.x, ax); ay = fmaf(a2, v2.y, ay);
            ax = fmaf(a3, v3.x, ax); ay = fmaf(a3, v3.y, ay);
        }
        for (; j < cnt; j++) {
            int s0 = sm_s[w][j];
            float a0 = sm_a[w][j];
            float2 v0 = *(const float2*)&h2[(size_t)s0 * 64 + lane * 2];
            den += a0;
            ax = fmaf(a0, v0.x, ax); ay = fmaf(a0, v0.y, ay);
        }
        __syncwarp();
    }
    const float inv = 1.f / den;
    float2 b = *(const float2*)&bias[lane * 2];
    float2 r = make_float2(fmaf(ax, inv, b.x), fmaf(ay, inv, b.y));
    *(float2*)&out[(size_t)n * 64 + lane * 2] = r;
}

// ---------------- launch ----------------
extern "C" void kernel_launch(void* const* d_in, const int* in_sizes, int n_in,
                              void* d_out, int out_size) {
    const float* x   = (const float*)d_in[0];
    const int*   ei  = (const int*)d_in[1];
    const float* W1  = (const float*)d_in[2];
    const float* as1 = (const float*)d_in[3];
    const float* ad1 = (const float*)d_in[4];
    const float* b1  = (const float*)d_in[5];
    const float* W2  = (const float*)d_in[6];
    const float* as2 = (const float*)d_in[7];
    const float* ad2 = (const float*)d_in[8];
    const float* b2  = (const float*)d_in[9];
    float* out = (float*)d_out;

    static cudaStream_t s2 = nullptr;
    static cudaEvent_t evFork = nullptr, evJoin = nullptr;
    if (!s2) {
        cudaStreamCreateWithFlags(&s2, cudaStreamNonBlocking);
        cudaEventCreateWithFlags(&evFork, cudaEventDisableTiming);
        cudaEventCreateWithFlags(&evJoin, cudaEventDisableTiming);
    }

    const int NCH = (N_NODES + 1023) / 1024;  // 49

    // Fork: CSR build on s2 overlaps convert+gemm1 on main.
    // gemm1 remains the 4th issued kernel (ncu capture slot).
    cudaEventRecord(evFork, 0);
    cudaStreamWaitEvent(s2, evFork, 0);

    init_deg_kernel<<<(N_NODES + 255) / 256, 256, 0, s2>>>();            // 1
    hist_kernel<<<(N_EDGES / 4 + 255) / 256, 256, 0, s2>>>(ei);          // 2
    convert_w_kernel<<<96, 256>>>(W1, W2);                               // 3 (main)
    gemm1_tc_kernel<<<(N_NODES + 127) / 128, 256>>>(x, as1, ad1);        // 4 (main)
    scan1_kernel<<<NCH, 1024, 0, s2>>>();                                // 5
    scan3_kernel<<<(N_NODES + 255) / 256, 256, 0, s2>>>(NCH);            // 6
    scatter_kernel<<<(N_EDGES / 4 + 255) / 256, 256, 0, s2>>>(ei);       // 7
    cudaEventRecord(evJoin, s2);

    cudaStreamWaitEvent(0, evJoin, 0);

    agg1_kernel<<<(N_NODES + 7) / 8, 256>>>(b1);
    gemm2_tc_kernel<<<(N_NODES + 127) / 128, 256>>>(as2, ad2);
    agg2_kernel<<<(N_NODES + 7) / 8, 256>>>(b2, out);
}

// round 12
// speedup vs baseline: 1.7910x; 1.0356x over previous
#include <cuda_runtime.h>
#include <cuda_bf16.h>
#include <cuda_fp16.h>
#include <math.h>

#define N_NODES 50000
#define N_EDGES 800000
#define ET (N_EDGES + N_NODES)

// ---------------- scratch (static device globals; no allocation) ----------------
__device__ __half g_h1h[(size_t)N_NODES * 128];  // layer1 features (fp16, gather-only)
__device__ float  g_out1[(size_t)N_NODES * 128]; // layer1 output (fp32, feeds gemm2)
__device__ __half g_h2h[(size_t)N_NODES * 64];   // layer2 features (fp16, gather-only)
__device__ float g_ss1[N_NODES * 4];
__device__ float g_sd1[N_NODES * 4];
__device__ float g_ss2[N_NODES];
__device__ float g_sd2[N_NODES];
__device__ int   g_deg[N_NODES];
__device__ int   g_off[N_NODES + 1];
__device__ int   g_pos[N_NODES];
__device__ int   g_esrc[ET];
__device__ int   g_chunk[64];
__device__ __nv_bfloat16 g_W1hi[128 * 128], g_W1lo[128 * 128];
__device__ __nv_bfloat16 g_W2hi[64 * 128],  g_W2lo[64 * 128];

__device__ __forceinline__ float lrelu(float x) {
    return x > 0.f ? x : 0.2f * x;
}
__device__ __forceinline__ int clampn(int v) {
    return min(max(v, 0), N_NODES - 1);
}

// ---------------- CSR build (self-loops pre-placed; int4 edge loads) ----------
__global__ void init_deg_kernel() {
    int i = blockIdx.x * blockDim.x + threadIdx.x;
    if (i < N_NODES) g_deg[i] = 1;  // self-loop
}

__global__ void hist_kernel(const int* __restrict__ ei) {
    int i = blockIdx.x * blockDim.x + threadIdx.x;
    if (i < N_EDGES / 4) {
        int4 d4 = ((const int4*)(ei + N_EDGES))[i];
        atomicAdd(&g_deg[clampn(d4.x)], 1);
        atomicAdd(&g_deg[clampn(d4.y)], 1);
        atomicAdd(&g_deg[clampn(d4.z)], 1);
        atomicAdd(&g_deg[clampn(d4.w)], 1);
    }
}

__global__ void scan1_kernel() {
    __shared__ int sm[1024];
    int i = blockIdx.x * 1024 + threadIdx.x;
    int v = (i < N_NODES) ? g_deg[i] : 0;
    sm[threadIdx.x] = v;
    __syncthreads();
#pragma unroll
    for (int o = 1; o < 1024; o <<= 1) {
        int t = (threadIdx.x >= o) ? sm[threadIdx.x - o] : 0;
        __syncthreads();
        sm[threadIdx.x] += t;
        __syncthreads();
    }
    if (i < N_NODES) g_off[i] = sm[threadIdx.x] - v;
    if (threadIdx.x == 1023) g_chunk[blockIdx.x] = sm[1023];
}

__global__ void scan3_kernel(int nch) {
    __shared__ int ch[64];
    int t = threadIdx.x;
    if (t < nch) ch[t] = g_chunk[t];
    __syncthreads();
    if (t == 0) {
        int acc = 0;
        for (int i = 0; i < nch; i++) { int v = ch[i]; ch[i] = acc; acc += v; }
    }
    __syncthreads();
    int i = blockIdx.x * blockDim.x + t;
    if (i < N_NODES) {
        int off = g_off[i] + ch[i >> 10];
        g_off[i] = off;
        g_pos[i] = 1;
        g_esrc[off] = i;  // self-loop at slot 0
    }
    if (i == 0) g_off[N_NODES] = ET;
}

__global__ void scatter_kernel(const int* __restrict__ ei) {
    int i = blockIdx.x * blockDim.x + threadIdx.x;
    if (i < N_EDGES / 4) {
        int4 s4 = ((const int4*)ei)[i];
        int4 d4 = ((const int4*)(ei + N_EDGES))[i];
        int s, d, p;
        s = clampn(s4.x); d = clampn(d4.x);
        p = atomicAdd(&g_pos[d], 1); g_esrc[g_off[d] + p] = s;
        s = clampn(s4.y); d = clampn(d4.y);
        p = atomicAdd(&g_pos[d], 1); g_esrc[g_off[d] + p] = s;
        s = clampn(s4.z); d = clampn(d4.z);
        p = atomicAdd(&g_pos[d], 1); g_esrc[g_off[d] + p] = s;
        s = clampn(s4.w); d = clampn(d4.w);
        p = atomicAdd(&g_pos[d], 1); g_esrc[g_off[d] + p] = s;
    }
}

// ---------------- weight pre-conversion (hi/lo bf16, transposed [n][k]) -------
__global__ void convert_w_kernel(const float* __restrict__ W1,
                                 const float* __restrict__ W2) {
    int i = blockIdx.x * blockDim.x + threadIdx.x;
    if (i < 128 * 128) {
        int k = i >> 7, n = i & 127;
        float v = W1[i];
        __nv_bfloat16 h = __float2bfloat16(v);
        g_W1hi[n * 128 + k] = h;
        g_W1lo[n * 128 + k] = __float2bfloat16(v - __bfloat162float(h));
    } else if (i < 128 * 128 + 128 * 64) {
        int j = i - 128 * 128;
        int k = j >> 6, n = j & 63;
        float v = W2[j];
        __nv_bfloat16 h = __float2bfloat16(v);
        g_W2hi[n * 128 + k] = h;
        g_W2lo[n * 128 + k] = __float2bfloat16(v - __bfloat162float(h));
    }
}

// ---------------- split-bf16 tensor-core GEMM + fused scores ----------------
__device__ __forceinline__ void cvt4(float4 v, uint2& h, uint2& l) {
    __nv_bfloat162 h01 = __floats2bfloat162_rn(v.x, v.y);
    __nv_bfloat162 h23 = __floats2bfloat162_rn(v.z, v.w);
    float2 f01 = __bfloat1622float2(h01);
    float2 f23 = __bfloat1622float2(h23);
    __nv_bfloat162 l01 = __floats2bfloat162_rn(v.x - f01.x, v.y - f01.y);
    __nv_bfloat162 l23 = __floats2bfloat162_rn(v.z - f23.x, v.w - f23.y);
    h = make_uint2(*(unsigned*)&h01, *(unsigned*)&h23);
    l = make_uint2(*(unsigned*)&l01, *(unsigned*)&l23);
}

#define MMA_BF16(c, a, b)                                                        \
    asm volatile(                                                                \
        "mma.sync.aligned.m16n8k16.row.col.f32.bf16.bf16.f32 "                   \
        "{%0,%1,%2,%3},{%4,%5,%6,%7},{%8,%9},{%0,%1,%2,%3};"                     \
        : "+f"((c)[0]), "+f"((c)[1]), "+f"((c)[2]), "+f"((c)[3])                 \
        : "r"((a)[0]), "r"((a)[1]), "r"((a)[2]), "r"((a)[3]),                    \
          "r"((b)[0]), "r"((b)[1]))

__device__ __forceinline__ float qreduce(float v) {
    v += __shfl_xor_sync(0xffffffffu, v, 1);
    v += __shfl_xor_sync(0xffffffffu, v, 2);
    return v;
}

// MODE 1: writes fp16 C + 4-head scores; MODE 2: fp16 C + 1-head scores.
template <int BN, int MODE>
__device__ void gemm_tc_dev(const float* __restrict__ A,
                            const __nv_bfloat16* __restrict__ Whi,
                            const __nv_bfloat16* __restrict__ Wlo,
                            __half* __restrict__ Ch, int M,
                            const float* __restrict__ a_src,
                            const float* __restrict__ a_dst,
                            float* __restrict__ ss, float* __restrict__ sd) {
    constexpr int WM = 32, MT = 2;
    constexpr int WN = BN / 2;
    constexpr int NT = WN / 8;
    constexpr int PAD = 40;

    __shared__ __align__(16) __nv_bfloat16 sAhi[128][PAD];
    __shared__ __align__(16) __nv_bfloat16 sAlo[128][PAD];
    __shared__ __align__(16) __nv_bfloat16 sBhi[BN][PAD];
    __shared__ __align__(16) __nv_bfloat16 sBlo[BN][PAD];
    __shared__ float sred_s[MODE == 2 ? 128 : 1][2];
    __shared__ float sred_d[MODE == 2 ? 128 : 1][2];

    const int tid = threadIdx.x;
    const int wid = tid >> 5, lane = tid & 31;
    const int row0 = blockIdx.x * 128;
    const int wm = wid >> 1, wn = wid & 1;

    float acc[MT][NT][4] = {};

    for (int kt = 0; kt < 128; kt += 32) {
#pragma unroll
        for (int i = 0; i < 4; i++) {
            int f4 = tid + i * 256;
            int r = f4 >> 3, c4 = (f4 & 7) * 4;
            float4 v = make_float4(0.f, 0.f, 0.f, 0.f);
            if (row0 + r < M)
                v = *(const float4*)(A + (size_t)(row0 + r) * 128 + kt + c4);
            uint2 h, l;
            cvt4(v, h, l);
            *(uint2*)&sAhi[r][c4] = h;
            *(uint2*)&sAlo[r][c4] = l;
        }
#pragma unroll
        for (int i = 0; i < BN / 32; i++) {
            int u = tid + i * 256;
            int n = u >> 3, c4 = (u & 7) * 4;
            *(uint2*)&sBhi[n][c4] = *(const uint2*)(Whi + n * 128 + kt + c4);
            *(uint2*)&sBlo[n][c4] = *(const uint2*)(Wlo + n * 128 + kt + c4);
        }
        __syncthreads();

#pragma unroll
        for (int ks = 0; ks < 32; ks += 16) {
            const int kk = ks + (lane & 3) * 2;
            unsigned ahi[MT][4], alo[MT][4], bhi[NT][2], blo[NT][2];
#pragma unroll
            for (int mi = 0; mi < MT; mi++) {
                int r0 = wm * WM + mi * 16 + (lane >> 2);
                ahi[mi][0] = *(const unsigned*)&sAhi[r0][kk];
                ahi[mi][1] = *(const unsigned*)&sAhi[r0 + 8][kk];
                ahi[mi][2] = *(const unsigned*)&sAhi[r0][kk + 8];
                ahi[mi][3] = *(const unsigned*)&sAhi[r0 + 8][kk + 8];
                alo[mi][0] = *(const unsigned*)&sAlo[r0][kk];
                alo[mi][1] = *(const unsigned*)&sAlo[r0 + 8][kk];
                alo[mi][2] = *(const unsigned*)&sAlo[r0][kk + 8];
                alo[mi][3] = *(const unsigned*)&sAlo[r0 + 8][kk + 8];
            }
#pragma unroll
            for (int ni = 0; ni < NT; ni++) {
                int n0 = wn * WN + ni * 8 + (lane >> 2);
                bhi[ni][0] = *(const unsigned*)&sBhi[n0][kk];
                bhi[ni][1] = *(const unsigned*)&sBhi[n0][kk + 8];
                blo[ni][0] = *(const unsigned*)&sBlo[n0][kk];
                blo[ni][1] = *(const unsigned*)&sBlo[n0][kk + 8];
            }
#pragma unroll
            for (int mi = 0; mi < MT; mi++)
#pragma unroll
                for (int ni = 0; ni < NT; ni++) MMA_BF16(acc[mi][ni], ahi[mi], bhi[ni]);
#pragma unroll
            for (int mi = 0; mi < MT; mi++)
#pragma unroll
                for (int ni = 0; ni < NT; ni++) MMA_BF16(acc[mi][ni], ahi[mi], blo[ni]);
#pragma unroll
            for (int mi = 0; mi < MT; mi++)
#pragma unroll
                for (int ni = 0; ni < NT; ni++) MMA_BF16(acc[mi][ni], alo[mi], bhi[ni]);
        }
        __syncthreads();
    }

    // ---- write C as fp16 (gather-only consumer)
#pragma unroll
    for (int mi = 0; mi < MT; mi++) {
#pragma unroll
        for (int ni = 0; ni < NT; ni++) {
            int r = row0 + wm * WM + mi * 16 + (lane >> 2);
            int c = wn * WN + ni * 8 + (lane & 3) * 2;
            if (r < M)
                *(__half2*)(Ch + (size_t)r * BN + c) =
                    __floats2half2_rn(acc[mi][ni][0], acc[mi][ni][1]);
            if (r + 8 < M)
                *(__half2*)(Ch + (size_t)(r + 8) * BN + c) =
                    __floats2half2_rn(acc[mi][ni][2], acc[mi][ni][3]);
        }
    }

    // ---- fused attention scores
    if (MODE == 1) {
        float ps[MT][2][2] = {}, pd[MT][2][2] = {};
#pragma unroll
        for (int ni = 0; ni < NT; ni++) {
            int c = wn * WN + ni * 8 + (lane & 3) * 2;
            float a0 = a_src[c], a1 = a_src[c + 1];
            float d0 = a_dst[c], d1 = a_dst[c + 1];
            int hb = ni >> 2;
#pragma unroll
            for (int mi = 0; mi < MT; mi++) {
                ps[mi][0][hb] += acc[mi][ni][0] * a0 + acc[mi][ni][1] * a1;
                ps[mi][1][hb] += acc[mi][ni][2] * a0 + acc[mi][ni][3] * a1;
                pd[mi][0][hb] += acc[mi][ni][0] * d0 + acc[mi][ni][1] * d1;
                pd[mi][1][hb] += acc[mi][ni][2] * d0 + acc[mi][ni][3] * d1;
            }
        }
#pragma unroll
        for (int mi = 0; mi < MT; mi++)
#pragma unroll
            for (int rh = 0; rh < 2; rh++)
#pragma unroll
                for (int hb = 0; hb < 2; hb++) {
                    float vs = qreduce(ps[mi][rh][hb]);
                    float vd = qreduce(pd[mi][rh][hb]);
                    if ((lane & 3) == 0) {
                        int r = row0 + wm * WM + mi * 16 + (lane >> 2) + rh * 8;
                        if (r < M) {
                            int head = wn * 2 + hb;
                            ss[(size_t)r * 4 + head] = vs;
                            sd[(size_t)r * 4 + head] = vd;
                        }
                    }
                }
    } else if (MODE == 2) {
        float ps[MT][2] = {}, pd[MT][2] = {};
#pragma unroll
        for (int ni = 0; ni < NT; ni++) {
            int c = wn * WN + ni * 8 + (lane & 3) * 2;
            float a0 = a_src[c], a1 = a_src[c + 1];
            float d0 = a_dst[c], d1 = a_dst[c + 1];
#pragma unroll
            for (int mi = 0; mi < MT; mi++) {
                ps[mi][0] += acc[mi][ni][0] * a0 + acc[mi][ni][1] * a1;
                ps[mi][1] += acc[mi][ni][2] * a0 + acc[mi][ni][3] * a1;
                pd[mi][0] += acc[mi][ni][0] * d0 + acc[mi][ni][1] * d1;
                pd[mi][1] += acc[mi][ni][2] * d0 + acc[mi][ni][3] * d1;
            }
        }
#pragma unroll
        for (int mi = 0; mi < MT; mi++)
#pragma unroll
            for (int rh = 0; rh < 2; rh++) {
                float vs = qreduce(ps[mi][rh]);
                float vd = qreduce(pd[mi][rh]);
                if ((lane & 3) == 0) {
                    int rl = wm * WM + mi * 16 + (lane >> 2) + rh * 8;
                    sred_s[rl][wn] = vs;
                    sred_d[rl][wn] = vd;
                }
            }
        __syncthreads();
        if (tid < 128) {
            int r = row0 + tid;
            if (r < M) {
                ss[r] = sred_s[tid][0] + sred_s[tid][1];
                sd[r] = sred_d[tid][0] + sred_d[tid][1];
            }
        }
    }
}

__global__ void __launch_bounds__(256, 2)
gemm1_tc_kernel(const float* __restrict__ x, const float* __restrict__ as1,
                const float* __restrict__ ad1) {
    gemm_tc_dev<128, 1>(x, g_W1hi, g_W1lo, g_h1h, N_NODES, as1, ad1, g_ss1, g_sd1);
}

__global__ void __launch_bounds__(256, 2)
gemm2_tc_kernel(const float* __restrict__ as2, const float* __restrict__ ad2) {
    gemm_tc_dev<64, 2>(g_out1, g_W2hi, g_W2lo, g_h2h, N_NODES, as2, ad2, g_ss2, g_sd2);
}

// ---------------- aggregation layer 1 (single-pass, fp16 gather) ----------------
__global__ void __launch_bounds__(256)
agg1_kernel(const float* __restrict__ bias) {
    const int w = threadIdx.x >> 5;
    const int lane = threadIdx.x & 31;
    const int n = blockIdx.x * 8 + w;

    __shared__ int   sm_s[8][32];
    __shared__ float sm_a[8][32][4];

    if (n >= N_NODES) return;
    const int beg = g_off[n];
    const int deg = g_off[n + 1] - beg;

    const float4 sdv = *(const float4*)(g_sd1 + n * 4);
    const int head = lane >> 3;
    float4 acc = make_float4(0.f, 0.f, 0.f, 0.f);
    float den = 0.f;
    const __half* __restrict__ h1 = g_h1h;

    for (int j0 = 0; j0 < deg; j0 += 32) {
        int cnt = min(32, deg - j0);
        if (lane < cnt) {
            int s = g_esrc[beg + j0 + lane];
            float4 ss = *(const float4*)(g_ss1 + s * 4);
            sm_s[w][lane] = s;
            sm_a[w][lane][0] = __expf(lrelu(ss.x + sdv.x));
            sm_a[w][lane][1] = __expf(lrelu(ss.y + sdv.y));
            sm_a[w][lane][2] = __expf(lrelu(ss.z + sdv.z));
            sm_a[w][lane][3] = __expf(lrelu(ss.w + sdv.w));
        }
        __syncwarp();
        int j = 0;
        for (; j + 4 <= cnt; j += 4) {
            int s0 = sm_s[w][j + 0], s1 = sm_s[w][j + 1];
            int s2 = sm_s[w][j + 2], s3 = sm_s[w][j + 3];
            float a0 = sm_a[w][j + 0][head], a1 = sm_a[w][j + 1][head];
            float a2 = sm_a[w][j + 2][head], a3 = sm_a[w][j + 3][head];
            __half2 p0 = *(const __half2*)&h1[(size_t)s0 * 128 + lane * 4];
            __half2 q0 = *(const __half2*)&h1[(size_t)s0 * 128 + lane * 4 + 2];
            __half2 p1 = *(const __half2*)&h1[(size_t)s1 * 128 + lane * 4];
            __half2 q1 = *(const __half2*)&h1[(size_t)s1 * 128 + lane * 4 + 2];
            __half2 p2 = *(const __half2*)&h1[(size_t)s2 * 128 + lane * 4];
            __half2 q2 = *(const __half2*)&h1[(size_t)s2 * 128 + lane * 4 + 2];
            __half2 p3 = *(const __half2*)&h1[(size_t)s3 * 128 + lane * 4];
            __half2 q3 = *(const __half2*)&h1[(size_t)s3 * 128 + lane * 4 + 2];
            den += a0 + a1 + a2 + a3;
            float2 f;
            f = __half22float2(p0); acc.x = fmaf(a0, f.x, acc.x); acc.y = fmaf(a0, f.y, acc.y);
            f = __half22float2(q0); acc.z = fmaf(a0, f.x, acc.z); acc.w = fmaf(a0, f.y, acc.w);
            f = __half22float2(p1); acc.x = fmaf(a1, f.x, acc.x); acc.y = fmaf(a1, f.y, acc.y);
            f = __half22float2(q1); acc.z = fmaf(a1, f.x, acc.z); acc.w = fmaf(a1, f.y, acc.w);
            f = __half22float2(p2); acc.x = fmaf(a2, f.x, acc.x); acc.y = fmaf(a2, f.y, acc.y);
            f = __half22float2(q2); acc.z = fmaf(a2, f.x, acc.z); acc.w = fmaf(a2, f.y, acc.w);
            f = __half22float2(p3); acc.x = fmaf(a3, f.x, acc.x); acc.y = fmaf(a3, f.y, acc.y);
            f = __half22float2(q3); acc.z = fmaf(a3, f.x, acc.z); acc.w = fmaf(a3, f.y, acc.w);
        }
        for (; j < cnt; j++) {
            int s0 = sm_s[w][j];
            float a0 = sm_a[w][j][head];
            __half2 p0 = *(const __half2*)&h1[(size_t)s0 * 128 + lane * 4];
            __half2 q0 = *(const __half2*)&h1[(size_t)s0 * 128 + lane * 4 + 2];
            den += a0;
            float2 f;
            f = __half22float2(p0); acc.x = fmaf(a0, f.x, acc.x); acc.y = fmaf(a0, f.y, acc.y);
            f = __half22float2(q0); acc.z = fmaf(a0, f.x, acc.z); acc.w = fmaf(a0, f.y, acc.w);
        }
        __syncwarp();
    }
    const float inv = 1.f / den;
    float4 b = *(const float4*)&bias[lane * 4];
    float4 r = make_float4(fmaxf(fmaf(acc.x, inv, b.x), 0.f),
                           fmaxf(fmaf(acc.y, inv, b.y), 0.f),
                           fmaxf(fmaf(acc.z, inv, b.z), 0.f),
                           fmaxf(fmaf(acc.w, inv, b.w), 0.f));
    *(float4*)&g_out1[(size_t)n * 128 + lane * 4] = r;
}

// ---------------- aggregation layer 2 (single-pass, fp16 gather) ----------------
__global__ void __launch_bounds__(256)
agg2_kernel(const float* __restrict__ bias, float* __restrict__ out) {
    const int w = threadIdx.x >> 5;
    const int lane = threadIdx.x & 31;
    const int n = blockIdx.x * 8 + w;

    __shared__ int   sm_s[8][32];
    __shared__ float sm_a[8][32];

    if (n >= N_NODES) return;
    const int beg = g_off[n];
    const int deg = g_off[n + 1] - beg;

    const float sd = g_sd2[n];
    float ax = 0.f, ay = 0.f, den = 0.f;
    const __half* __restrict__ h2 = g_h2h;

    for (int j0 = 0; j0 < deg; j0 += 32) {
        int cnt = min(32, deg - j0);
        if (lane < cnt) {
            int s = g_esrc[beg + j0 + lane];
            sm_s[w][lane] = s;
            sm_a[w][lane] = __expf(lrelu(g_ss2[s] + sd));
        }
        __syncwarp();
        int j = 0;
        for (; j + 4 <= cnt; j += 4) {
            int s0 = sm_s[w][j + 0], s1 = sm_s[w][j + 1];
            int s2 = sm_s[w][j + 2], s3 = sm_s[w][j + 3];
            float a0 = sm_a[w][j + 0], a1 = sm_a[w][j + 1];
            float a2 = sm_a[w][j + 2], a3 = sm_a[w][j + 3];
            __half2 v0 = *(const __half2*)&h2[(size_t)s0 * 64 + lane * 2];
            __half2 v1 = *(const __half2*)&h2[(size_t)s1 * 64 + lane * 2];
            __half2 v2 = *(const __half2*)&h2[(size_t)s2 * 64 + lane * 2];
            __half2 v3 = *(const __half2*)&h2[(size_t)s3 * 64 + lane * 2];
            den += a0 + a1 + a2 + a3;
            float2 f;
            f = __half22float2(v0); ax = fmaf(a0, f.x, ax); ay = fmaf(a0, f.y, ay);
            f = __half22float2(v1); ax = fmaf(a1, f.x, ax); ay = fmaf(a1, f.y, ay);
            f = __half22float2(v2); ax = fmaf(a2, f.x, ax); ay = fmaf(a2, f.y, ay);
            f = __half22float2(v3); ax = fmaf(a3, f.x, ax); ay = fmaf(a3, f.y, ay);
        }
        for (; j < cnt; j++) {
            int s0 = sm_s[w][j];
            float a0 = sm_a[w][j];
            __half2 v0 = *(const __half2*)&h2[(size_t)s0 * 64 + lane * 2];
            den += a0;
            float2 f = __half22float2(v0);
            ax = fmaf(a0, f.x, ax); ay = fmaf(a0, f.y, ay);
        }
        __syncwarp();
    }
    const float inv = 1.f / den;
    float2 b = *(const float2*)&bias[lane * 2];
    float2 r = make_float2(fmaf(ax, inv, b.x), fmaf(ay, inv, b.y));
    *(float2*)&out[(size_t)n * 64 + lane * 2] = r;
}

// ---------------- launch ----------------
extern "C" void kernel_launch(void* const* d_in, const int* in_sizes, int n_in,
                              void* d_out, int out_size) {
    const float* x   = (const float*)d_in[0];
    const int*   ei  = (const int*)d_in[1];
    const float* W1  = (const float*)d_in[2];
    const float* as1 = (const float*)d_in[3];
    const float* ad1 = (const float*)d_in[4];
    const float* b1  = (const float*)d_in[5];
    const float* W2  = (const float*)d_in[6];
    const float* as2 = (const float*)d_in[7];
    const float* ad2 = (const float*)d_in[8];
    const float* b2  = (const float*)d_in[9];
    float* out = (float*)d_out;

    static cudaStream_t s2 = nullptr;
    static cudaEvent_t evFork = nullptr, evJoin = nullptr;
    if (!s2) {
        cudaStreamCreateWithFlags(&s2, cudaStreamNonBlocking);
        cudaEventCreateWithFlags(&evFork, cudaEventDisableTiming);
        cudaEventCreateWithFlags(&evJoin, cudaEventDisableTiming);
    }

    const int NCH = (N_NODES + 1023) / 1024;  // 49

    cudaEventRecord(evFork, 0);
    cudaStreamWaitEvent(s2, evFork, 0);

    init_deg_kernel<<<(N_NODES + 255) / 256, 256, 0, s2>>>();            // 1
    hist_kernel<<<(N_EDGES / 4 + 255) / 256, 256, 0, s2>>>(ei);          // 2
    convert_w_kernel<<<96, 256>>>(W1, W2);                               // 3 (main)
    gemm1_tc_kernel<<<(N_NODES + 127) / 128, 256>>>(x, as1, ad1);        // 4 (main)
    scan1_kernel<<<NCH, 1024, 0, s2>>>();                                // 5
    scan3_kernel<<<(N_NODES + 255) / 256, 256, 0, s2>>>(NCH);            // 6
    scatter_kernel<<<(N_EDGES / 4 + 255) / 256, 256, 0, s2>>>(ei);       // 7
    cudaEventRecord(evJoin, s2);

    cudaStreamWaitEvent(0, evJoin, 0);

    agg1_kernel<<<(N_NODES + 7) / 8, 256>>>(b1);
    gemm2_tc_kernel<<<(N_NODES + 127) / 128, 256>>>(as2, ad2);
    agg2_kernel<<<(N_NODES + 7) / 8, 256>>>(b2, out);
}

// round 13
// speedup vs baseline: 1.7934x; 1.0014x over previous
#include <cuda_runtime.h>
#include <cuda_bf16.h>
#include <cuda_fp16.h>
#include <math.h>

#define N_NODES 50000
#define N_EDGES 800000
#define ET (N_EDGES + N_NODES)

// ---------------- scratch (static device globals; no allocation) ----------------
__device__ __half g_h1h[(size_t)N_NODES * 128];   // layer1 features (fp16, gather-only)
__device__ __nv_bfloat16 g_O1hi[(size_t)N_NODES * 128];  // layer1 out split-bf16 (feeds gemm2)
__device__ __nv_bfloat16 g_O1lo[(size_t)N_NODES * 128];
__device__ __half g_h2h[(size_t)N_NODES * 64];    // layer2 features (fp16, gather-only)
__device__ float g_ss1[N_NODES * 4];
__device__ float g_sd1[N_NODES * 4];
__device__ float g_ss2[N_NODES];
__device__ float g_sd2[N_NODES];
__device__ __align__(16) int g_deg[N_NODES];
__device__ __align__(16) int g_off[N_NODES + 4];
__device__ int   g_pos[N_NODES];
__device__ int   g_esrc[ET];
__device__ int   g_chunk[64];
__device__ __nv_bfloat16 g_W1hi[128 * 128], g_W1lo[128 * 128];
__device__ __nv_bfloat16 g_W2hi[64 * 128],  g_W2lo[64 * 128];

__device__ __forceinline__ float lrelu(float x) {
    return x > 0.f ? x : 0.2f * x;
}
__device__ __forceinline__ int clampn(int v) {
    return min(max(v, 0), N_NODES - 1);
}

// ---------------- CSR build ----------------
__global__ void init_deg_kernel() {
    int i = blockIdx.x * blockDim.x + threadIdx.x;
    if (i < N_NODES) g_deg[i] = 1;  // self-loop
}

__global__ void hist_kernel(const int* __restrict__ ei) {
    int i = blockIdx.x * blockDim.x + threadIdx.x;
    if (i < N_EDGES / 4) {
        int4 d4 = ((const int4*)(ei + N_EDGES))[i];
        atomicAdd(&g_deg[clampn(d4.x)], 1);
        atomicAdd(&g_deg[clampn(d4.y)], 1);
        atomicAdd(&g_deg[clampn(d4.z)], 1);
        atomicAdd(&g_deg[clampn(d4.w)], 1);
    }
}

// warp-shuffle scan, 4 elems/thread. N_NODES divisible by 4 (12500 int4s).
// grid = 13 blocks x 1024 threads (13312 int4 slots >= 12500).
__global__ void scan1_kernel() {
    __shared__ int wsum[32];
    int idx = blockIdx.x * 1024 + threadIdx.x;  // int4 index
    int4 v = make_int4(0, 0, 0, 0);
    if (idx < N_NODES / 4) v = ((const int4*)g_deg)[idx];
    int s1 = v.x + v.y, s2 = s1 + v.z, s3 = s2 + v.w;
    int lane = threadIdx.x & 31, w = threadIdx.x >> 5;
    int sc = s3;  // inclusive scan of per-thread totals within warp
#pragma unroll
    for (int o = 1; o < 32; o <<= 1) {
        int t = __shfl_up_sync(0xffffffffu, sc, o);
        if (lane >= o) sc += t;
    }
    if (lane == 31) wsum[w] = sc;
    __syncthreads();
    if (w == 0) {
        int t = wsum[lane];
        int s = t;
#pragma unroll
        for (int o = 1; o < 32; o <<= 1) {
            int u = __shfl_up_sync(0xffffffffu, s, o);
            if (lane >= o) s += u;
        }
        wsum[lane] = s - t;  // exclusive warp base
        if (lane == 31) g_chunk[blockIdx.x] = s;  // block total
    }
    __syncthreads();
    int base = wsum[w] + (sc - s3);  // exclusive prefix for this thread
    if (idx < N_NODES / 4)
        ((int4*)g_off)[idx] = make_int4(base, base + v.x, base + s1, base + s2);
}

// chunk-prefix (13 entries) + offset fixup + self-loop placement
__global__ void scan3_kernel(int nch) {
    __shared__ int ch[16];
    int t = threadIdx.x;
    if (t < nch) ch[t] = g_chunk[t];
    __syncthreads();
    if (t == 0) {
        int acc = 0;
        for (int i = 0; i < nch; i++) { int v = ch[i]; ch[i] = acc; acc += v; }
    }
    __syncthreads();
    int i = blockIdx.x * blockDim.x + t;
    if (i < N_NODES) {
        int off = g_off[i] + ch[i >> 12];  // 4096 nodes per chunk
        g_off[i] = off;
        g_pos[i] = 1;
        g_esrc[off] = i;  // self-loop at slot 0
    }
    if (i == 0) g_off[N_NODES] = ET;
}

__global__ void scatter_kernel(const int* __restrict__ ei) {
    int i = blockIdx.x * blockDim.x + threadIdx.x;
    if (i < N_EDGES / 4) {
        int4 s4 = ((const int4*)ei)[i];
        int4 d4 = ((const int4*)(ei + N_EDGES))[i];
        int s, d, p;
        s = clampn(s4.x); d = clampn(d4.x);
        p = atomicAdd(&g_pos[d], 1); g_esrc[g_off[d] + p] = s;
        s = clampn(s4.y); d = clampn(d4.y);
        p = atomicAdd(&g_pos[d], 1); g_esrc[g_off[d] + p] = s;
        s = clampn(s4.z); d = clampn(d4.z);
        p = atomicAdd(&g_pos[d], 1); g_esrc[g_off[d] + p] = s;
        s = clampn(s4.w); d = clampn(d4.w);
        p = atomicAdd(&g_pos[d], 1); g_esrc[g_off[d] + p] = s;
    }
}

// ---------------- weight pre-conversion (hi/lo bf16, transposed [n][k]) -------
__global__ void convert_w_kernel(const float* __restrict__ W1,
                                 const float* __restrict__ W2) {
    int i = blockIdx.x * blockDim.x + threadIdx.x;
    if (i < 128 * 128) {
        int k = i >> 7, n = i & 127;
        float v = W1[i];
        __nv_bfloat16 h = __float2bfloat16(v);
        g_W1hi[n * 128 + k] = h;
        g_W1lo[n * 128 + k] = __float2bfloat16(v - __bfloat162float(h));
    } else if (i < 128 * 128 + 128 * 64) {
        int j = i - 128 * 128;
        int k = j >> 6, n = j & 63;
        float v = W2[j];
        __nv_bfloat16 h = __float2bfloat16(v);
        g_W2hi[n * 128 + k] = h;
        g_W2lo[n * 128 + k] = __float2bfloat16(v - __bfloat162float(h));
    }
}

// ---------------- split-bf16 tensor-core GEMM + fused scores ----------------
__device__ __forceinline__ void cvt4(float4 v, uint2& h, uint2& l) {
    __nv_bfloat162 h01 = __floats2bfloat162_rn(v.x, v.y);
    __nv_bfloat162 h23 = __floats2bfloat162_rn(v.z, v.w);
    float2 f01 = __bfloat1622float2(h01);
    float2 f23 = __bfloat1622float2(h23);
    __nv_bfloat162 l01 = __floats2bfloat162_rn(v.x - f01.x, v.y - f01.y);
    __nv_bfloat162 l23 = __floats2bfloat162_rn(v.z - f23.x, v.w - f23.y);
    h = make_uint2(*(unsigned*)&h01, *(unsigned*)&h23);
    l = make_uint2(*(unsigned*)&l01, *(unsigned*)&l23);
}

#define MMA_BF16(c, a, b)                                                        \
    asm volatile(                                                                \
        "mma.sync.aligned.m16n8k16.row.col.f32.bf16.bf16.f32 "                   \
        "{%0,%1,%2,%3},{%4,%5,%6,%7},{%8,%9},{%0,%1,%2,%3};"                     \
        : "+f"((c)[0]), "+f"((c)[1]), "+f"((c)[2]), "+f"((c)[3])                 \
        : "r"((a)[0]), "r"((a)[1]), "r"((a)[2]), "r"((a)[3]),                    \
          "r"((b)[0]), "r"((b)[1]))

__device__ __forceinline__ float qreduce(float v) {
    v += __shfl_xor_sync(0xffffffffu, v, 1);
    v += __shfl_xor_sync(0xffffffffu, v, 2);
    return v;
}

// MODE 1: A fp32 (convert), 4-head fused scores.
// MODE 2: A pre-split bf16 (plain copy), 1-head fused scores.
template <int BN, int MODE>
__device__ void gemm_tc_dev(const float* __restrict__ A,
                            const __nv_bfloat16* __restrict__ Ahi,
                            const __nv_bfloat16* __restrict__ Alo,
                            const __nv_bfloat16* __restrict__ Whi,
                            const __nv_bfloat16* __restrict__ Wlo,
                            __half* __restrict__ Ch, int M,
                            const float* __restrict__ a_src,
                            const float* __restrict__ a_dst,
                            float* __restrict__ ss, float* __restrict__ sd) {
    constexpr int WM = 32, MT = 2;
    constexpr int WN = BN / 2;
    constexpr int NT = WN / 8;
    constexpr int PAD = 40;

    __shared__ __align__(16) __nv_bfloat16 sAhi[128][PAD];
    __shared__ __align__(16) __nv_bfloat16 sAlo[128][PAD];
    __shared__ __align__(16) __nv_bfloat16 sBhi[BN][PAD];
    __shared__ __align__(16) __nv_bfloat16 sBlo[BN][PAD];
    __shared__ float sred_s[MODE == 2 ? 128 : 1][2];
    __shared__ float sred_d[MODE == 2 ? 128 : 1][2];

    const int tid = threadIdx.x;
    const int wid = tid >> 5, lane = tid & 31;
    const int row0 = blockIdx.x * 128;
    const int wm = wid >> 1, wn = wid & 1;

    float acc[MT][NT][4] = {};

    for (int kt = 0; kt < 128; kt += 32) {
#pragma unroll
        for (int i = 0; i < 4; i++) {
            int f4 = tid + i * 256;
            int r = f4 >> 3, c4 = (f4 & 7) * 4;
            if (MODE == 1) {
                float4 v = make_float4(0.f, 0.f, 0.f, 0.f);
                if (row0 + r < M)
                    v = *(const float4*)(A + (size_t)(row0 + r) * 128 + kt + c4);
                uint2 h, l;
                cvt4(v, h, l);
                *(uint2*)&sAhi[r][c4] = h;
                *(uint2*)&sAlo[r][c4] = l;
            } else {
                uint2 h = make_uint2(0u, 0u), l = make_uint2(0u, 0u);
                if (row0 + r < M) {
                    h = *(const uint2*)(Ahi + (size_t)(row0 + r) * 128 + kt + c4);
                    l = *(const uint2*)(Alo + (size_t)(row0 + r) * 128 + kt + c4);
                }
                *(uint2*)&sAhi[r][c4] = h;
                *(uint2*)&sAlo[r][c4] = l;
            }
        }
#pragma unroll
        for (int i = 0; i < BN / 32; i++) {
            int u = tid + i * 256;
            int n = u >> 3, c4 = (u & 7) * 4;
            *(uint2*)&sBhi[n][c4] = *(const uint2*)(Whi + n * 128 + kt + c4);
            *(uint2*)&sBlo[n][c4] = *(const uint2*)(Wlo + n * 128 + kt + c4);
        }
        __syncthreads();

#pragma unroll
        for (int ks = 0; ks < 32; ks += 16) {
            const int kk = ks + (lane & 3) * 2;
            unsigned ahi[MT][4], alo[MT][4], bhi[NT][2], blo[NT][2];
#pragma unroll
            for (int mi = 0; mi < MT; mi++) {
                int r0 = wm * WM + mi * 16 + (lane >> 2);
                ahi[mi][0] = *(const unsigned*)&sAhi[r0][kk];
                ahi[mi][1] = *(const unsigned*)&sAhi[r0 + 8][kk];
                ahi[mi][2] = *(const unsigned*)&sAhi[r0][kk + 8];
                ahi[mi][3] = *(const unsigned*)&sAhi[r0 + 8][kk + 8];
                alo[mi][0] = *(const unsigned*)&sAlo[r0][kk];
                alo[mi][1] = *(const unsigned*)&sAlo[r0 + 8][kk];
                alo[mi][2] = *(const unsigned*)&sAlo[r0][kk + 8];
                alo[mi][3] = *(const unsigned*)&sAlo[r0 + 8][kk + 8];
            }
#pragma unroll
            for (int ni = 0; ni < NT; ni++) {
                int n0 = wn * WN + ni * 8 + (lane >> 2);
                bhi[ni][0] = *(const unsigned*)&sBhi[n0][kk];
                bhi[ni][1] = *(const unsigned*)&sBhi[n0][kk + 8];
                blo[ni][0] = *(const unsigned*)&sBlo[n0][kk];
                blo[ni][1] = *(const unsigned*)&sBlo[n0][kk + 8];
            }
#pragma unroll
            for (int mi = 0; mi < MT; mi++)
#pragma unroll
                for (int ni = 0; ni < NT; ni++) MMA_BF16(acc[mi][ni], ahi[mi], bhi[ni]);
#pragma unroll
            for (int mi = 0; mi < MT; mi++)
#pragma unroll
                for (int ni = 0; ni < NT; ni++) MMA_BF16(acc[mi][ni], ahi[mi], blo[ni]);
#pragma unroll
            for (int mi = 0; mi < MT; mi++)
#pragma unroll
                for (int ni = 0; ni < NT; ni++) MMA_BF16(acc[mi][ni], alo[mi], bhi[ni]);
        }
        __syncthreads();
    }

    // ---- write C as fp16 (gather-only consumer)
#pragma unroll
    for (int mi = 0; mi < MT; mi++) {
#pragma unroll
        for (int ni = 0; ni < NT; ni++) {
            int r = row0 + wm * WM + mi * 16 + (lane >> 2);
            int c = wn * WN + ni * 8 + (lane & 3) * 2;
            if (r < M)
                *(__half2*)(Ch + (size_t)r * BN + c) =
                    __floats2half2_rn(acc[mi][ni][0], acc[mi][ni][1]);
            if (r + 8 < M)
                *(__half2*)(Ch + (size_t)(r + 8) * BN + c) =
                    __floats2half2_rn(acc[mi][ni][2], acc[mi][ni][3]);
        }
    }

    // ---- fused attention scores
    if (MODE == 1) {
        float ps[MT][2][2] = {}, pd[MT][2][2] = {};
#pragma unroll
        for (int ni = 0; ni < NT; ni++) {
            int c = wn * WN + ni * 8 + (lane & 3) * 2;
            float a0 = a_src[c], a1 = a_src[c + 1];
            float d0 = a_dst[c], d1 = a_dst[c + 1];
            int hb = ni >> 2;
#pragma unroll
            for (int mi = 0; mi < MT; mi++) {
                ps[mi][0][hb] += acc[mi][ni][0] * a0 + acc[mi][ni][1] * a1;
                ps[mi][1][hb] += acc[mi][ni][2] * a0 + acc[mi][ni][3] * a1;
                pd[mi][0][hb] += acc[mi][ni][0] * d0 + acc[mi][ni][1] * d1;
                pd[mi][1][hb] += acc[mi][ni][2] * d0 + acc[mi][ni][3] * d1;
            }
        }
#pragma unroll
        for (int mi = 0; mi < MT; mi++)
#pragma unroll
            for (int rh = 0; rh < 2; rh++)
#pragma unroll
                for (int hb = 0; hb < 2; hb++) {
                    float vs = qreduce(ps[mi][rh][hb]);
                    float vd = qreduce(pd[mi][rh][hb]);
                    if ((lane & 3) == 0) {
                        int r = row0 + wm * WM + mi * 16 + (lane >> 2) + rh * 8;
                        if (r < M) {
                            int head = wn * 2 + hb;
                            ss[(size_t)r * 4 + head] = vs;
                            sd[(size_t)r * 4 + head] = vd;
                        }
                    }
                }
    } else if (MODE == 2) {
        float ps[MT][2] = {}, pd[MT][2] = {};
#pragma unroll
        for (int ni = 0; ni < NT; ni++) {
            int c = wn * WN + ni * 8 + (lane & 3) * 2;
            float a0 = a_src[c], a1 = a_src[c + 1];
            float d0 = a_dst[c], d1 = a_dst[c + 1];
#pragma unroll
            for (int mi = 0; mi < MT; mi++) {
                ps[mi][0] += acc[mi][ni][0] * a0 + acc[mi][ni][1] * a1;
                ps[mi][1] += acc[mi][ni][2] * a0 + acc[mi][ni][3] * a1;
                pd[mi][0] += acc[mi][ni][0] * d0 + acc[mi][ni][1] * d1;
                pd[mi][1] += acc[mi][ni][2] * d0 + acc[mi][ni][3] * d1;
            }
        }
#pragma unroll
        for (int mi = 0; mi < MT; mi++)
#pragma unroll
            for (int rh = 0; rh < 2; rh++) {
                float vs = qreduce(ps[mi][rh]);
                float vd = qreduce(pd[mi][rh]);
                if ((lane & 3) == 0) {
                    int rl = wm * WM + mi * 16 + (lane >> 2) + rh * 8;
                    sred_s[rl][wn] = vs;
                    sred_d[rl][wn] = vd;
                }
            }
        __syncthreads();
        if (tid < 128) {
            int r = row0 + tid;
            if (r < M) {
                ss[r] = sred_s[tid][0] + sred_s[tid][1];
                sd[r] = sred_d[tid][0] + sred_d[tid][1];
            }
        }
    }
}

__global__ void __launch_bounds__(256, 2)
gemm1_tc_kernel(const float* __restrict__ x, const float* __restrict__ as1,
                const float* __restrict__ ad1) {
    gemm_tc_dev<128, 1>(x, nullptr, nullptr, g_W1hi, g_W1lo, g_h1h, N_NODES,
                        as1, ad1, g_ss1, g_sd1);
}

__global__ void __launch_bounds__(256, 2)
gemm2_tc_kernel(const float* __restrict__ as2, const float* __restrict__ ad2) {
    gemm_tc_dev<64, 2>(nullptr, g_O1hi, g_O1lo, g_W2hi, g_W2lo, g_h2h, N_NODES,
                       as2, ad2, g_ss2, g_sd2);
}

// ---------------- aggregation layer 1 (single-pass, fp16 LDG.64 gather) --------
__global__ void __launch_bounds__(256)
agg1_kernel(const float* __restrict__ bias) {
    const int w = threadIdx.x >> 5;
    const int lane = threadIdx.x & 31;
    const int n = blockIdx.x * 8 + w;

    __shared__ int   sm_s[8][32];
    __shared__ float sm_a[8][32][4];

    if (n >= N_NODES) return;
    const int beg = g_off[n];
    const int deg = g_off[n + 1] - beg;

    const float4 sdv = *(const float4*)(g_sd1 + n * 4);
    const int head = lane >> 3;
    float4 acc = make_float4(0.f, 0.f, 0.f, 0.f);
    float den = 0.f;
    const __half* __restrict__ h1 = g_h1h;

    for (int j0 = 0; j0 < deg; j0 += 32) {
        int cnt = min(32, deg - j0);
        if (lane < cnt) {
            int s = g_esrc[beg + j0 + lane];
            float4 ss = *(const float4*)(g_ss1 + s * 4);
            sm_s[w][lane] = s;
            sm_a[w][lane][0] = __expf(lrelu(ss.x + sdv.x));
            sm_a[w][lane][1] = __expf(lrelu(ss.y + sdv.y));
            sm_a[w][lane][2] = __expf(lrelu(ss.z + sdv.z));
            sm_a[w][lane][3] = __expf(lrelu(ss.w + sdv.w));
        }
        __syncwarp();
        int j = 0;
        for (; j + 4 <= cnt; j += 4) {
            int s0 = sm_s[w][j + 0], s1 = sm_s[w][j + 1];
            int s2 = sm_s[w][j + 2], s3 = sm_s[w][j + 3];
            float a0 = sm_a[w][j + 0][head], a1 = sm_a[w][j + 1][head];
            float a2 = sm_a[w][j + 2][head], a3 = sm_a[w][j + 3][head];
            uint2 u0 = *(const uint2*)&h1[(size_t)s0 * 128 + lane * 4];
            uint2 u1 = *(const uint2*)&h1[(size_t)s1 * 128 + lane * 4];
            uint2 u2 = *(const uint2*)&h1[(size_t)s2 * 128 + lane * 4];
            uint2 u3 = *(const uint2*)&h1[(size_t)s3 * 128 + lane * 4];
            den += a0 + a1 + a2 + a3;
            float2 f;
            f = __half22float2(*(__half2*)&u0.x); acc.x = fmaf(a0, f.x, acc.x); acc.y = fmaf(a0, f.y, acc.y);
            f = __half22float2(*(__half2*)&u0.y); acc.z = fmaf(a0, f.x, acc.z); acc.w = fmaf(a0, f.y, acc.w);
            f = __half22float2(*(__half2*)&u1.x); acc.x = fmaf(a1, f.x, acc.x); acc.y = fmaf(a1, f.y, acc.y);
            f = __half22float2(*(__half2*)&u1.y); acc.z = fmaf(a1, f.x, acc.z); acc.w = fmaf(a1, f.y, acc.w);
            f = __half22float2(*(__half2*)&u2.x); acc.x = fmaf(a2, f.x, acc.x); acc.y = fmaf(a2, f.y, acc.y);
            f = __half22float2(*(__half2*)&u2.y); acc.z = fmaf(a2, f.x, acc.z); acc.w = fmaf(a2, f.y, acc.w);
            f = __half22float2(*(__half2*)&u3.x); acc.x = fmaf(a3, f.x, acc.x); acc.y = fmaf(a3, f.y, acc.y);
            f = __half22float2(*(__half2*)&u3.y); acc.z = fmaf(a3, f.x, acc.z); acc.w = fmaf(a3, f.y, acc.w);
        }
        for (; j < cnt; j++) {
            int s0 = sm_s[w][j];
            float a0 = sm_a[w][j][head];
            uint2 u0 = *(const uint2*)&h1[(size_t)s0 * 128 + lane * 4];
            den += a0;
            float2 f;
            f = __half22float2(*(__half2*)&u0.x); acc.x = fmaf(a0, f.x, acc.x); acc.y = fmaf(a0, f.y, acc.y);
            f = __half22float2(*(__half2*)&u0.y); acc.z = fmaf(a0, f.x, acc.z); acc.w = fmaf(a0, f.y, acc.w);
        }
        __syncwarp();
    }
    const float inv = 1.f / den;
    float4 b = *(const float4*)&bias[lane * 4];
    float4 r = make_float4(fmaxf(fmaf(acc.x, inv, b.x), 0.f),
                           fmaxf(fmaf(acc.y, inv, b.y), 0.f),
                           fmaxf(fmaf(acc.z, inv, b.z), 0.f),
                           fmaxf(fmaf(acc.w, inv, b.w), 0.f));
    // write out1 as split hi/lo bf16 (feeds gemm2 directly)
    uint2 hh, ll;
    cvt4(r, hh, ll);
    *(uint2*)&g_O1hi[(size_t)n * 128 + lane * 4] = hh;
    *(uint2*)&g_O1lo[(size_t)n * 128 + lane * 4] = ll;
}

// ---------------- aggregation layer 2 (single-pass, fp16 gather) ----------------
__global__ void __launch_bounds__(256)
agg2_kernel(const float* __restrict__ bias, float* __restrict__ out) {
    const int w = threadIdx.x >> 5;
    const int lane = threadIdx.x & 31;
    const int n = blockIdx.x * 8 + w;

    __shared__ int   sm_s[8][32];
    __shared__ float sm_a[8][32];

    if (n >= N_NODES) return;
    const int beg = g_off[n];
    const int deg = g_off[n + 1] - beg;

    const float sd = g_sd2[n];
    float ax = 0.f, ay = 0.f, den = 0.f;
    const __half* __restrict__ h2 = g_h2h;

    for (int j0 = 0; j0 < deg; j0 += 32) {
        int cnt = min(32, deg - j0);
        if (lane < cnt) {
            int s = g_esrc[beg + j0 + lane];
            sm_s[w][lane] = s;
            sm_a[w][lane] = __expf(lrelu(g_ss2[s] + sd));
        }
        __syncwarp();
        int j = 0;
        for (; j + 4 <= cnt; j += 4) {
            int s0 = sm_s[w][j + 0], s1 = sm_s[w][j + 1];
            int s2 = sm_s[w][j + 2], s3 = sm_s[w][j + 3];
            float a0 = sm_a[w][j + 0], a1 = sm_a[w][j + 1];
            float a2 = sm_a[w][j + 2], a3 = sm_a[w][j + 3];
            __half2 v0 = *(const __half2*)&h2[(size_t)s0 * 64 + lane * 2];
            __half2 v1 = *(const __half2*)&h2[(size_t)s1 * 64 + lane * 2];
            __half2 v2 = *(const __half2*)&h2[(size_t)s2 * 64 + lane * 2];
            __half2 v3 = *(const __half2*)&h2[(size_t)s3 * 64 + lane * 2];
            den += a0 + a1 + a2 + a3;
            float2 f;
            f = __half22float2(v0); ax = fmaf(a0, f.x, ax); ay = fmaf(a0, f.y, ay);
            f = __half22float2(v1); ax = fmaf(a1, f.x, ax); ay = fmaf(a1, f.y, ay);
            f = __half22float2(v2); ax = fmaf(a2, f.x, ax); ay = fmaf(a2, f.y, ay);
            f = __half22float2(v3); ax = fmaf(a3, f.x, ax); ay = fmaf(a3, f.y, ay);
        }
        for (; j < cnt; j++) {
            int s0 = sm_s[w][j];
            float a0 = sm_a[w][j];
            __half2 v0 = *(const __half2*)&h2[(size_t)s0 * 64 + lane * 2];
            den += a0;
            float2 f = __half22float2(v0);
            ax = fmaf(a0, f.x, ax); ay = fmaf(a0, f.y, ay);
        }
        __syncwarp();
    }
    const float inv = 1.f / den;
    float2 b = *(const float2*)&bias[lane * 2];
    float2 r = make_float2(fmaf(ax, inv, b.x), fmaf(ay, inv, b.y));
    *(float2*)&out[(size_t)n * 64 + lane * 2] = r;
}

// ---------------- launch ----------------
extern "C" void kernel_launch(void* const* d_in, const int* in_sizes, int n_in,
                              void* d_out, int out_size) {
    const float* x   = (const float*)d_in[0];
    const int*   ei  = (const int*)d_in[1];
    const float* W1  = (const float*)d_in[2];
    const float* as1 = (const float*)d_in[3];
    const float* ad1 = (const float*)d_in[4];
    const float* b1  = (const float*)d_in[5];
    const float* W2  = (const float*)d_in[6];
    const float* as2 = (const float*)d_in[7];
    const float* ad2 = (const float*)d_in[8];
    const float* b2  = (const float*)d_in[9];
    float* out = (float*)d_out;

    static cudaStream_t s2 = nullptr;
    static cudaEvent_t evFork = nullptr, evJoin = nullptr;
    if (!s2) {
        cudaStreamCreateWithFlags(&s2, cudaStreamNonBlocking);
        cudaEventCreateWithFlags(&evFork, cudaEventDisableTiming);
        cudaEventCreateWithFlags(&evJoin, cudaEventDisableTiming);
    }

    const int NCH = (N_NODES / 4 + 1023) / 1024;  // 13 chunks of 4096 nodes

    cudaEventRecord(evFork, 0);
    cudaStreamWaitEvent(s2, evFork, 0);

    init_deg_kernel<<<(N_NODES + 255) / 256, 256, 0, s2>>>();            // 1
    hist_kernel<<<(N_EDGES / 4 + 255) / 256, 256, 0, s2>>>(ei);          // 2
    convert_w_kernel<<<96, 256>>>(W1, W2);                               // 3 (main)
    gemm1_tc_kernel<<<(N_NODES + 127) / 128, 256>>>(x, as1, ad1);        // 4 (main)
    scan1_kernel<<<NCH, 1024, 0, s2>>>();                                // 5
    scan3_kernel<<<(N_NODES + 255) / 256, 256, 0, s2>>>(NCH);            // 6
    scatter_kernel<<<(N_EDGES / 4 + 255) / 256, 256, 0, s2>>>(ei);       // 7
    cudaEventRecord(evJoin, s2);

    cudaStreamWaitEvent(0, evJoin, 0);

    agg1_kernel<<<(N_NODES + 7) / 8, 256>>>(b1);
    gemm2_tc_kernel<<<(N_NODES + 127) / 128, 256>>>(as2, ad2);
    agg2_kernel<<<(N_NODES + 7) / 8, 256>>>(b2, out);
}

// round 15
// speedup vs baseline: 1.8041x; 1.0060x over previous
#include <cuda_runtime.h>
#include <cuda_bf16.h>
#include <cuda_fp16.h>
#include <cstdint>
#include <math.h>

#define N_NODES 50000
#define N_EDGES 800000
#define ET (N_EDGES + N_NODES)

// ---------------- scratch (static device globals; no allocation) ----------------
__device__ __half g_h1h[(size_t)N_NODES * 128];   // layer1 features (fp16, gather-only)
__device__ __nv_bfloat16 g_O1hi[(size_t)N_NODES * 128];  // layer1 out split-bf16
__device__ __nv_bfloat16 g_O1lo[(size_t)N_NODES * 128];
__device__ __half g_h2h[(size_t)N_NODES * 64];    // layer2 features (fp16, gather-only)
__device__ float g_ss1[N_NODES * 4];
__device__ float g_sd1[N_NODES * 4];
__device__ float g_ss2[N_NODES];
__device__ float g_sd2[N_NODES];
__device__ __align__(16) int g_deg[N_NODES];
__device__ __align__(16) int g_off[N_NODES + 4];
__device__ int   g_pos[N_NODES];
__device__ int   g_esrc[ET];
__device__ int   g_chunk[64];
__device__ __nv_bfloat16 g_W1hi[128 * 128], g_W1lo[128 * 128];
__device__ __nv_bfloat16 g_W2hi[64 * 128],  g_W2lo[64 * 128];

__device__ __forceinline__ float lrelu(float x) {
    return x > 0.f ? x : 0.2f * x;
}
__device__ __forceinline__ int clampn(int v) {
    return min(max(v, 0), N_NODES - 1);
}

// ---------------- CSR build ----------------
__global__ void init_deg_kernel() {
    int i = blockIdx.x * blockDim.x + threadIdx.x;
    if (i < N_NODES) g_deg[i] = 1;  // self-loop
}

__global__ void hist_kernel(const int* __restrict__ ei) {
    int i = blockIdx.x * blockDim.x + threadIdx.x;
    if (i < N_EDGES / 4) {
        int4 d4 = ((const int4*)(ei + N_EDGES))[i];
        atomicAdd(&g_deg[clampn(d4.x)], 1);
        atomicAdd(&g_deg[clampn(d4.y)], 1);
        atomicAdd(&g_deg[clampn(d4.z)], 1);
        atomicAdd(&g_deg[clampn(d4.w)], 1);
    }
}

// warp-shuffle scan, 4 elems/thread (int4).
__global__ void scan1_kernel() {
    __shared__ int wsum[32];
    int idx = blockIdx.x * 1024 + threadIdx.x;
    int4 v = make_int4(0, 0, 0, 0);
    if (idx < N_NODES / 4) v = ((const int4*)g_deg)[idx];
    int s1 = v.x + v.y, s2 = s1 + v.z, s3 = s2 + v.w;
    int lane = threadIdx.x & 31, w = threadIdx.x >> 5;
    int sc = s3;
#pragma unroll
    for (int o = 1; o < 32; o <<= 1) {
        int t = __shfl_up_sync(0xffffffffu, sc, o);
        if (lane >= o) sc += t;
    }
    if (lane == 31) wsum[w] = sc;
    __syncthreads();
    if (w == 0) {
        int t = wsum[lane];
        int s = t;
#pragma unroll
        for (int o = 1; o < 32; o <<= 1) {
            int u = __shfl_up_sync(0xffffffffu, s, o);
            if (lane >= o) s += u;
        }
        wsum[lane] = s - t;
        if (lane == 31) g_chunk[blockIdx.x] = s;
    }
    __syncthreads();
    int base = wsum[w] + (sc - s3);
    if (idx < N_NODES / 4)
        ((int4*)g_off)[idx] = make_int4(base, base + v.x, base + s1, base + s2);
}

__global__ void scan3_kernel(int nch) {
    __shared__ int ch[16];
    int t = threadIdx.x;
    if (t < nch) ch[t] = g_chunk[t];
    __syncthreads();
    if (t == 0) {
        int acc = 0;
        for (int i = 0; i < nch; i++) { int v = ch[i]; ch[i] = acc; acc += v; }
    }
    __syncthreads();
    int i = blockIdx.x * blockDim.x + t;
    if (i < N_NODES) {
        int off = g_off[i] + ch[i >> 12];
        g_off[i] = off;
        g_pos[i] = 1;
        g_esrc[off] = i;  // self-loop at slot 0
    }
    if (i == 0) g_off[N_NODES] = ET;
}

__global__ void scatter_kernel(const int* __restrict__ ei) {
    int i = blockIdx.x * blockDim.x + threadIdx.x;
    if (i < N_EDGES / 4) {
        int4 s4 = ((const int4*)ei)[i];
        int4 d4 = ((const int4*)(ei + N_EDGES))[i];
        int s, d, p;
        s = clampn(s4.x); d = clampn(d4.x);
        p = atomicAdd(&g_pos[d], 1); g_esrc[g_off[d] + p] = s;
        s = clampn(s4.y); d = clampn(d4.y);
        p = atomicAdd(&g_pos[d], 1); g_esrc[g_off[d] + p] = s;
        s = clampn(s4.z); d = clampn(d4.z);
        p = atomicAdd(&g_pos[d], 1); g_esrc[g_off[d] + p] = s;
        s = clampn(s4.w); d = clampn(d4.w);
        p = atomicAdd(&g_pos[d], 1); g_esrc[g_off[d] + p] = s;
    }
}

// ---------------- weight pre-conversion (hi/lo bf16, transposed [n][k]) -------
__global__ void convert_w_kernel(const float* __restrict__ W1,
                                 const float* __restrict__ W2) {
    int i = blockIdx.x * blockDim.x + threadIdx.x;
    if (i < 128 * 128) {
        int k = i >> 7, n = i & 127;
        float v = W1[i];
        __nv_bfloat16 h = __float2bfloat16(v);
        g_W1hi[n * 128 + k] = h;
        g_W1lo[n * 128 + k] = __float2bfloat16(v - __bfloat162float(h));
    } else if (i < 128 * 128 + 128 * 64) {
        int j = i - 128 * 128;
        int k = j >> 6, n = j & 63;
        float v = W2[j];
        __nv_bfloat16 h = __float2bfloat16(v);
        g_W2hi[n * 128 + k] = h;
        g_W2lo[n * 128 + k] = __float2bfloat16(v - __bfloat162float(h));
    }
}

// ---------------- split-bf16 tensor-core GEMM + fused scores ----------------
__device__ __forceinline__ void cvt4(float4 v, uint2& h, uint2& l) {
    __nv_bfloat162 h01 = __floats2bfloat162_rn(v.x, v.y);
    __nv_bfloat162 h23 = __floats2bfloat162_rn(v.z, v.w);
    float2 f01 = __bfloat1622float2(h01);
    float2 f23 = __bfloat1622float2(h23);
    __nv_bfloat162 l01 = __floats2bfloat162_rn(v.x - f01.x, v.y - f01.y);
    __nv_bfloat162 l23 = __floats2bfloat162_rn(v.z - f23.x, v.w - f23.y);
    h = make_uint2(*(unsigned*)&h01, *(unsigned*)&h23);
    l = make_uint2(*(unsigned*)&l01, *(unsigned*)&l23);
}

#define MMA_BF16(c, a, b)                                                        \
    asm volatile(                                                                \
        "mma.sync.aligned.m16n8k16.row.col.f32.bf16.bf16.f32 "                   \
        "{%0,%1,%2,%3},{%4,%5,%6,%7},{%8,%9},{%0,%1,%2,%3};"                     \
        : "+f"((c)[0]), "+f"((c)[1]), "+f"((c)[2]), "+f"((c)[3])                 \
        : "r"((a)[0]), "r"((a)[1]), "r"((a)[2]), "r"((a)[3]),                    \
          "r"((b)[0]), "r"((b)[1]))

#define LDSM_X4(r0, r1, r2, r3, addr)                                            \
    asm volatile("ldmatrix.sync.aligned.m8n8.x4.shared.b16 {%0,%1,%2,%3}, [%4];" \
                 : "=r"(r0), "=r"(r1), "=r"(r2), "=r"(r3) : "r"(addr))

__device__ __forceinline__ float qreduce(float v) {
    v += __shfl_xor_sync(0xffffffffu, v, 1);
    v += __shfl_xor_sync(0xffffffffu, v, 2);
    return v;
}

// MODE 1: A fp32 (convert), 4-head fused scores.
// MODE 2: A pre-split bf16 (plain copy), 1-head fused scores.
template <int BN, int MODE>
__device__ void gemm_tc_dev(const float* __restrict__ A,
                            const __nv_bfloat16* __restrict__ Ahi,
                            const __nv_bfloat16* __restrict__ Alo,
                            const __nv_bfloat16* __restrict__ Whi,
                            const __nv_bfloat16* __restrict__ Wlo,
                            __half* __restrict__ Ch, int M,
                            const float* __restrict__ a_src,
                            const float* __restrict__ a_dst,
                            float* __restrict__ ss, float* __restrict__ sd) {
    constexpr int WM = 32, MT = 2;
    constexpr int WN = BN / 2;
    constexpr int NT = WN / 8;
    constexpr int PAD = 40;

    __shared__ __align__(16) __nv_bfloat16 sAhi[128][PAD];
    __shared__ __align__(16) __nv_bfloat16 sAlo[128][PAD];
    __shared__ __align__(16) __nv_bfloat16 sBhi[BN][PAD];
    __shared__ __align__(16) __nv_bfloat16 sBlo[BN][PAD];
    __shared__ float sred_s[MODE == 2 ? 128 : 1][2];
    __shared__ float sred_d[MODE == 2 ? 128 : 1][2];

    const int tid = threadIdx.x;
    const int wid = tid >> 5, lane = tid & 31;
    const int row0 = blockIdx.x * 128;
    const int wm = wid >> 1, wn = wid & 1;

    // ldmatrix per-lane address offsets
    const int a_row = (lane & 7) + ((lane >> 3) & 1) * 8;  // row within 16
    const int a_col = (lane >> 4) * 8;                     // k offset 0/8
    const int b_n   = (lane & 7) + ((lane >> 4) & 1) * 8;  // n within 16
    const int b_k   = ((lane >> 3) & 1) * 8;               // k offset 0/8

    const unsigned uAhi = (unsigned)__cvta_generic_to_shared(&sAhi[0][0]);
    const unsigned uAlo = (unsigned)__cvta_generic_to_shared(&sAlo[0][0]);
    const unsigned uBhi = (unsigned)__cvta_generic_to_shared(&sBhi[0][0]);
    const unsigned uBlo = (unsigned)__cvta_generic_to_shared(&sBlo[0][0]);

    float acc[MT][NT][4] = {};

    for (int kt = 0; kt < 128; kt += 32) {
#pragma unroll
        for (int i = 0; i < 4; i++) {
            int f4 = tid + i * 256;
            int r = f4 >> 3, c4 = (f4 & 7) * 4;
            if (MODE == 1) {
                float4 v = make_float4(0.f, 0.f, 0.f, 0.f);
                if (row0 + r < M)
                    v = *(const float4*)(A + (size_t)(row0 + r) * 128 + kt + c4);
                uint2 h, l;
                cvt4(v, h, l);
                *(uint2*)&sAhi[r][c4] = h;
                *(uint2*)&sAlo[r][c4] = l;
            } else {
                uint2 h = make_uint2(0u, 0u), l = make_uint2(0u, 0u);
                if (row0 + r < M) {
                    h = *(const uint2*)(Ahi + (size_t)(row0 + r) * 128 + kt + c4);
                    l = *(const uint2*)(Alo + (size_t)(row0 + r) * 128 + kt + c4);
                }
                *(uint2*)&sAhi[r][c4] = h;
                *(uint2*)&sAlo[r][c4] = l;
            }
        }
#pragma unroll
        for (int i = 0; i < BN / 32; i++) {
            int u = tid + i * 256;
            int n = u >> 3, c4 = (u & 7) * 4;
            *(uint2*)&sBhi[n][c4] = *(const uint2*)(Whi + n * 128 + kt + c4);
            *(uint2*)&sBlo[n][c4] = *(const uint2*)(Wlo + n * 128 + kt + c4);
        }
        __syncthreads();

#pragma unroll
        for (int ks = 0; ks < 32; ks += 16) {
            unsigned ahi[MT][4], alo[MT][4], bhi[NT][2], blo[NT][2];
#pragma unroll
            for (int mi = 0; mi < MT; mi++) {
                unsigned off =
                    (unsigned)((wm * WM + mi * 16 + a_row) * PAD + ks + a_col) * 2u;
                LDSM_X4(ahi[mi][0], ahi[mi][1], ahi[mi][2], ahi[mi][3], uAhi + off);
                LDSM_X4(alo[mi][0], alo[mi][1], alo[mi][2], alo[mi][3], uAlo + off);
            }
#pragma unroll
            for (int np = 0; np < NT; np += 2) {
                unsigned off =
                    (unsigned)((wn * WN + np * 8 + b_n) * PAD + ks + b_k) * 2u;
                LDSM_X4(bhi[np][0], bhi[np][1], bhi[np + 1][0], bhi[np + 1][1],
                        uBhi + off);
                LDSM_X4(blo[np][0], blo[np][1], blo[np + 1][0], blo[np + 1][1],
                        uBlo + off);
            }
#pragma unroll
            for (int mi = 0; mi < MT; mi++)
#pragma unroll
                for (int ni = 0; ni < NT; ni++) MMA_BF16(acc[mi][ni], ahi[mi], bhi[ni]);
#pragma unroll
            for (int mi = 0; mi < MT; mi++)
#pragma unroll
                for (int ni = 0; ni < NT; ni++) MMA_BF16(acc[mi][ni], ahi[mi], blo[ni]);
#pragma unroll
            for (int mi = 0; mi < MT; mi++)
#pragma unroll
                for (int ni = 0; ni < NT; ni++) MMA_BF16(acc[mi][ni], alo[mi], bhi[ni]);
        }
        __syncthreads();
    }

    // ---- write C as fp16 (gather-only consumer)
#pragma unroll
    for (int mi = 0; mi < MT; mi++) {
#pragma unroll
        for (int ni = 0; ni < NT; ni++) {
            int r = row0 + wm * WM + mi * 16 + (lane >> 2);
            int c = wn * WN + ni * 8 + (lane & 3) * 2;
            if (r < M)
                *(__half2*)(Ch + (size_t)r * BN + c) =
                    __floats2half2_rn(acc[mi][ni][0], acc[mi][ni][1]);
            if (r + 8 < M)
                *(__half2*)(Ch + (size_t)(r + 8) * BN + c) =
                    __floats2half2_rn(acc[mi][ni][2], acc[mi][ni][3]);
        }
    }

    // ---- fused attention scores
    if (MODE == 1) {
        float ps[MT][2][2] = {}, pd[MT][2][2] = {};
#pragma unroll
        for (int ni = 0; ni < NT; ni++) {
            int c = wn * WN + ni * 8 + (lane & 3) * 2;
            float a0 = a_src[c], a1 = a_src[c + 1];
            float d0 = a_dst[c], d1 = a_dst[c + 1];
            int hb = ni >> 2;
#pragma unroll
            for (int mi = 0; mi < MT; mi++) {
                ps[mi][0][hb] += acc[mi][ni][0] * a0 + acc[mi][ni][1] * a1;
                ps[mi][1][hb] += acc[mi][ni][2] * a0 + acc[mi][ni][3] * a1;
                pd[mi][0][hb] += acc[mi][ni][0] * d0 + acc[mi][ni][1] * d1;
                pd[mi][1][hb] += acc[mi][ni][2] * d0 + acc[mi][ni][3] * d1;
            }
        }
#pragma unroll
        for (int mi = 0; mi < MT; mi++)
#pragma unroll
            for (int rh = 0; rh < 2; rh++)
#pragma unroll
                for (int hb = 0; hb < 2; hb++) {
                    float vs = qreduce(ps[mi][rh][hb]);
                    float vd = qreduce(pd[mi][rh][hb]);
                    if ((lane & 3) == 0) {
                        int r = row0 + wm * WM + mi * 16 + (lane >> 2) + rh * 8;
                        if (r < M) {
                            int head = wn * 2 + hb;
                            ss[(size_t)r * 4 + head] = vs;
                            sd[(size_t)r * 4 + head] = vd;
                        }
                    }
                }
    } else if (MODE == 2) {
        float ps[MT][2] = {}, pd[MT][2] = {};
#pragma unroll
        for (int ni = 0; ni < NT; ni++) {
            int c = wn * WN + ni * 8 + (lane & 3) * 2;
            float a0 = a_src[c], a1 = a_src[c + 1];
            float d0 = a_dst[c], d1 = a_dst[c + 1];
#pragma unroll
            for (int mi = 0; mi < MT; mi++) {
                ps[mi][0] += acc[mi][ni][0] * a0 + acc[mi][ni][1] * a1;
                ps[mi][1] += acc[mi][ni][2] * a0 + acc[mi][ni][3] * a1;
                pd[mi][0] += acc[mi][ni][0] * d0 + acc[mi][ni][1] * d1;
                pd[mi][1] += acc[mi][ni][2] * d0 + acc[mi][ni][3] * d1;
            }
        }
#pragma unroll
        for (int mi = 0; mi < MT; mi++)
#pragma unroll
            for (int rh = 0; rh < 2; rh++) {
                float vs = qreduce(ps[mi][rh]);
                float vd = qreduce(pd[mi][rh]);
                if ((lane & 3) == 0) {
                    int rl = wm * WM + mi * 16 + (lane >> 2) + rh * 8;
                    sred_s[rl][wn] = vs;
                    sred_d[rl][wn] = vd;
                }
            }
        __syncthreads();
        if (tid < 128) {
            int r = row0 + tid;
            if (r < M) {
                ss[r] = sred_s[tid][0] + sred_s[tid][1];
                sd[r] = sred_d[tid][0] + sred_d[tid][1];
            }
        }
    }
}

__global__ void __launch_bounds__(256, 2)
gemm1_tc_kernel(const float* __restrict__ x, const float* __restrict__ as1,
                const float* __restrict__ ad1) {
    gemm_tc_dev<128, 1>(x, nullptr, nullptr, g_W1hi, g_W1lo, g_h1h, N_NODES,
                        as1, ad1, g_ss1, g_sd1);
}

__global__ void __launch_bounds__(256, 2)
gemm2_tc_kernel(const float* __restrict__ as2, const float* __restrict__ ad2) {
    gemm_tc_dev<64, 2>(nullptr, g_O1hi, g_O1lo, g_W2hi, g_W2lo, g_h2h, N_NODES,
                       as2, ad2, g_ss2, g_sd2);
}

// ---------------- aggregation layer 1 (single-pass, unroll-8 gather) ----------
__global__ void __launch_bounds__(256)
agg1_kernel(const float* __restrict__ bias) {
    const int w = threadIdx.x >> 5;
    const int lane = threadIdx.x & 31;
    const int n = blockIdx.x * 8 + w;

    __shared__ int   sm_s[8][32];
    __shared__ float sm_a[8][32][4];

    if (n >= N_NODES) return;
    const int beg = g_off[n];
    const int deg = g_off[n + 1] - beg;

    const float4 sdv = *(const float4*)(g_sd1 + n * 4);
    const int head = lane >> 3;
    float4 acc = make_float4(0.f, 0.f, 0.f, 0.f);
    float den = 0.f;
    const __half* __restrict__ h1 = g_h1h;

    for (int j0 = 0; j0 < deg; j0 += 32) {
        int cnt = min(32, deg - j0);
        if (lane < cnt) {
            int s = g_esrc[beg + j0 + lane];
            float4 ss = *(const float4*)(g_ss1 + s * 4);
            sm_s[w][lane] = s;
            sm_a[w][lane][0] = __expf(lrelu(ss.x + sdv.x));
            sm_a[w][lane][1] = __expf(lrelu(ss.y + sdv.y));
            sm_a[w][lane][2] = __expf(lrelu(ss.z + sdv.z));
            sm_a[w][lane][3] = __expf(lrelu(ss.w + sdv.w));
        }
        __syncwarp();
        int j = 0;
        for (; j + 8 <= cnt; j += 8) {
            int   sj[8];
            float aj[8];
            uint2 uj[8];
#pragma unroll
            for (int q = 0; q < 8; q++) {
                sj[q] = sm_s[w][j + q];
                aj[q] = sm_a[w][j + q][head];
            }
#pragma unroll
            for (int q = 0; q < 8; q++)
                uj[q] = *(const uint2*)&h1[(size_t)sj[q] * 128 + lane * 4];
#pragma unroll
            for (int q = 0; q < 8; q++) {
                den += aj[q];
                float2 f;
                f = __half22float2(*(__half2*)&uj[q].x);
                acc.x = fmaf(aj[q], f.x, acc.x); acc.y = fmaf(aj[q], f.y, acc.y);
                f = __half22float2(*(__half2*)&uj[q].y);
                acc.z = fmaf(aj[q], f.x, acc.z); acc.w = fmaf(aj[q], f.y, acc.w);
            }
        }
        for (; j < cnt; j++) {
            int s0 = sm_s[w][j];
            float a0 = sm_a[w][j][head];
            uint2 u0 = *(const uint2*)&h1[(size_t)s0 * 128 + lane * 4];
            den += a0;
            float2 f;
            f = __half22float2(*(__half2*)&u0.x);
            acc.x = fmaf(a0, f.x, acc.x); acc.y = fmaf(a0, f.y, acc.y);
            f = __half22float2(*(__half2*)&u0.y);
            acc.z = fmaf(a0, f.x, acc.z); acc.w = fmaf(a0, f.y, acc.w);
        }
        __syncwarp();
    }
    const float inv = 1.f / den;
    float4 b = *(const float4*)&bias[lane * 4];
    float4 r = make_float4(fmaxf(fmaf(acc.x, inv, b.x), 0.f),
                           fmaxf(fmaf(acc.y, inv, b.y), 0.f),
                           fmaxf(fmaf(acc.z, inv, b.z), 0.f),
                           fmaxf(fmaf(acc.w, inv, b.w), 0.f));
    uint2 hh, ll;
    cvt4(r, hh, ll);
    *(uint2*)&g_O1hi[(size_t)n * 128 + lane * 4] = hh;
    *(uint2*)&g_O1lo[(size_t)n * 128 + lane * 4] = ll;
}

// ---------------- aggregation layer 2 (single-pass, unroll-8 gather) ----------
__global__ void __launch_bounds__(256)
agg2_kernel(const float* __restrict__ bias, float* __restrict__ out) {
    const int w = threadIdx.x >> 5;
    const int lane = threadIdx.x & 31;
    const int n = blockIdx.x * 8 + w;

    __shared__ int   sm_s[8][32];
    __shared__ float sm_a[8][32];

    if (n >= N_NODES) return;
    const int beg = g_off[n];
    const int deg = g_off[n + 1] - beg;

    const float sd = g_sd2[n];
    float ax = 0.f, ay = 0.f, den = 0.f;
    const __half* __restrict__ h2 = g_h2h;

    for (int j0 = 0; j0 < deg; j0 += 32) {
        int cnt = min(32, deg - j0);
        if (lane < cnt) {
            int s = g_esrc[beg + j0 + lane];
            sm_s[w][lane] = s;
            sm_a[w][lane] = __expf(lrelu(g_ss2[s] + sd));
        }
        __syncwarp();
        int j = 0;
        for (; j + 8 <= cnt; j += 8) {
            int     sj[8];
            float   aj[8];
            __half2 vj[8];
#pragma unroll
            for (int q = 0; q < 8; q++) {
                sj[q] = sm_s[w][j + q];
                aj[q] = sm_a[w][j + q];
            }
#pragma unroll
            for (int q = 0; q < 8; q++)
                vj[q] = *(const __half2*)&h2[(size_t)sj[q] * 64 + lane * 2];
#pragma unroll
            for (int q = 0; q < 8; q++) {
                den += aj[q];
                float2 f = __half22float2(vj[q]);
                ax = fmaf(aj[q], f.x, ax);
                ay = fmaf(aj[q], f.y, ay);
            }
        }
        for (; j < cnt; j++) {
            int s0 = sm_s[w][j];
            float a0 = sm_a[w][j];
            __half2 v0 = *(const __half2*)&h2[(size_t)s0 * 64 + lane * 2];
            den += a0;
            float2 f = __half22float2(v0);
            ax = fmaf(a0, f.x, ax); ay = fmaf(a0, f.y, ay);
        }
        __syncwarp();
    }
    const float inv = 1.f / den;
    float2 b = *(const float2*)&bias[lane * 2];
    float2 r = make_float2(fmaf(ax, inv, b.x), fmaf(ay, inv, b.y));
    *(float2*)&out[(size_t)n * 64 + lane * 2] = r;
}

// ---------------- launch ----------------
extern "C" void kernel_launch(void* const* d_in, const int* in_sizes, int n_in,
                              void* d_out, int out_size) {
    const float* x   = (const float*)d_in[0];
    const int*   ei  = (const int*)d_in[1];
    const float* W1  = (const float*)d_in[2];
    const float* as1 = (const float*)d_in[3];
    const float* ad1 = (const float*)d_in[4];
    const float* b1  = (const float*)d_in[5];
    const float* W2  = (const float*)d_in[6];
    const float* as2 = (const float*)d_in[7];
    const float* ad2 = (const float*)d_in[8];
    const float* b2  = (const float*)d_in[9];
    float* out = (float*)d_out;

    static cudaStream_t s2 = nullptr;
    static cudaEvent_t evFork = nullptr, evJoin = nullptr;
    if (!s2) {
        cudaStreamCreateWithFlags(&s2, cudaStreamNonBlocking);
        cudaEventCreateWithFlags(&evFork, cudaEventDisableTiming);
        cudaEventCreateWithFlags(&evJoin, cudaEventDisableTiming);
    }

    const int NCH = (N_NODES / 4 + 1023) / 1024;  // 13 chunks of 4096 nodes

    cudaEventRecord(evFork, 0);
    cudaStreamWaitEvent(s2, evFork, 0);

    init_deg_kernel<<<(N_NODES + 255) / 256, 256, 0, s2>>>();            // 1
    hist_kernel<<<(N_EDGES / 4 + 255) / 256, 256, 0, s2>>>(ei);          // 2
    convert_w_kernel<<<96, 256>>>(W1, W2);                               // 3 (main)
    gemm1_tc_kernel<<<(N_NODES + 127) / 128, 256>>>(x, as1, ad1);        // 4 (main)
    scan1_kernel<<<NCH, 1024, 0, s2>>>();                                // 5
    scan3_kernel<<<(N_NODES + 255) / 256, 256, 0, s2>>>(NCH);            // 6
    scatter_kernel<<<(N_EDGES / 4 + 255) / 256, 256, 0, s2>>>(ei);       // 7
    cudaEventRecord(evJoin, s2);

    cudaStreamWaitEvent(0, evJoin, 0);

    agg1_kernel<<<(N_NODES + 7) / 8, 256>>>(b1);
    gemm2_tc_kernel<<<(N_NODES + 127) / 128, 256>>>(as2, ad2);
    agg2_kernel<<<(N_NODES + 7) / 8, 256>>>(b2, out);
}

// round 16
// speedup vs baseline: 2.0210x; 1.1202x over previous
#include <cuda_runtime.h>
#include <cuda_bf16.h>
#include <cuda_fp16.h>
#include <cstdint>
#include <math.h>

#define N_NODES 50000
#define N_EDGES 800000
#define ET (N_EDGES + N_NODES)

// ---------------- scratch (static device globals; no allocation) ----------------
__device__ __half g_h1h[(size_t)N_NODES * 128];  // layer1 features (fp16, gather)
__device__ __half g_O1h[(size_t)N_NODES * 128];  // layer1 out fp16 (feeds gemm2 A)
__device__ __half g_h2h[(size_t)N_NODES * 64];   // layer2 features (fp16, gather)
__device__ float g_ss1[N_NODES * 4];
__device__ float g_sd1[N_NODES * 4];
__device__ float g_ss2[N_NODES];
__device__ float g_sd2[N_NODES];
__device__ __align__(16) int g_deg[N_NODES];
__device__ __align__(16) int g_off[N_NODES + 4];
__device__ int   g_pos[N_NODES];
__device__ int   g_esrc[ET];
__device__ int   g_chunk[64];
__device__ __half g_W1h[128 * 128];  // transposed [n][k], fp16
__device__ __half g_W2h[64 * 128];

__device__ __forceinline__ float lrelu(float x) {
    return x > 0.f ? x : 0.2f * x;
}
__device__ __forceinline__ int clampn(int v) {
    return min(max(v, 0), N_NODES - 1);
}

// ---------------- CSR build ----------------
__global__ void init_deg_kernel() {
    int i = blockIdx.x * blockDim.x + threadIdx.x;
    if (i < N_NODES) g_deg[i] = 1;  // self-loop
}

__global__ void hist_kernel(const int* __restrict__ ei) {
    int i = blockIdx.x * blockDim.x + threadIdx.x;
    if (i < N_EDGES / 4) {
        int4 d4 = ((const int4*)(ei + N_EDGES))[i];
        atomicAdd(&g_deg[clampn(d4.x)], 1);
        atomicAdd(&g_deg[clampn(d4.y)], 1);
        atomicAdd(&g_deg[clampn(d4.z)], 1);
        atomicAdd(&g_deg[clampn(d4.w)], 1);
    }
}

__global__ void scan1_kernel() {
    __shared__ int wsum[32];
    int idx = blockIdx.x * 1024 + threadIdx.x;
    int4 v = make_int4(0, 0, 0, 0);
    if (idx < N_NODES / 4) v = ((const int4*)g_deg)[idx];
    int s1 = v.x + v.y, s2 = s1 + v.z, s3 = s2 + v.w;
    int lane = threadIdx.x & 31, w = threadIdx.x >> 5;
    int sc = s3;
#pragma unroll
    for (int o = 1; o < 32; o <<= 1) {
        int t = __shfl_up_sync(0xffffffffu, sc, o);
        if (lane >= o) sc += t;
    }
    if (lane == 31) wsum[w] = sc;
    __syncthreads();
    if (w == 0) {
        int t = wsum[lane];
        int s = t;
#pragma unroll
        for (int o = 1; o < 32; o <<= 1) {
            int u = __shfl_up_sync(0xffffffffu, s, o);
            if (lane >= o) s += u;
        }
        wsum[lane] = s - t;
        if (lane == 31) g_chunk[blockIdx.x] = s;
    }
    __syncthreads();
    int base = wsum[w] + (sc - s3);
    if (idx < N_NODES / 4)
        ((int4*)g_off)[idx] = make_int4(base, base + v.x, base + s1, base + s2);
}

__global__ void scan3_kernel(int nch) {
    __shared__ int ch[16];
    int t = threadIdx.x;
    if (t < nch) ch[t] = g_chunk[t];
    __syncthreads();
    if (t == 0) {
        int acc = 0;
        for (int i = 0; i < nch; i++) { int v = ch[i]; ch[i] = acc; acc += v; }
    }
    __syncthreads();
    int i = blockIdx.x * blockDim.x + t;
    if (i < N_NODES) {
        int off = g_off[i] + ch[i >> 12];
        g_off[i] = off;
        g_pos[i] = 1;
        g_esrc[off] = i;  // self-loop at slot 0
    }
    if (i == 0) g_off[N_NODES] = ET;
}

__global__ void scatter_kernel(const int* __restrict__ ei) {
    int i = blockIdx.x * blockDim.x + threadIdx.x;
    if (i < N_EDGES / 4) {
        int4 s4 = ((const int4*)ei)[i];
        int4 d4 = ((const int4*)(ei + N_EDGES))[i];
        int s, d, p;
        s = clampn(s4.x); d = clampn(d4.x);
        p = atomicAdd(&g_pos[d], 1); g_esrc[g_off[d] + p] = s;
        s = clampn(s4.y); d = clampn(d4.y);
        p = atomicAdd(&g_pos[d], 1); g_esrc[g_off[d] + p] = s;
        s = clampn(s4.z); d = clampn(d4.z);
        p = atomicAdd(&g_pos[d], 1); g_esrc[g_off[d] + p] = s;
        s = clampn(s4.w); d = clampn(d4.w);
        p = atomicAdd(&g_pos[d], 1); g_esrc[g_off[d] + p] = s;
    }
}

// ---------------- weight pre-conversion (fp16, transposed [n][k]) ------------
__global__ void convert_w_kernel(const float* __restrict__ W1,
                                 const float* __restrict__ W2) {
    int i = blockIdx.x * blockDim.x + threadIdx.x;
    if (i < 128 * 128) {
        int k = i >> 7, n = i & 127;
        g_W1h[n * 128 + k] = __float2half_rn(W1[i]);
    } else if (i < 128 * 128 + 128 * 64) {
        int j = i - 128 * 128;
        int k = j >> 6, n = j & 63;
        g_W2h[n * 128 + k] = __float2half_rn(W2[j]);
    }
}

// ---------------- fp16 tensor-core GEMM + fused scores ----------------
#define MMA_F16(c, a, b)                                                         \
    asm volatile(                                                                \
        "mma.sync.aligned.m16n8k16.row.col.f32.f16.f16.f32 "                     \
        "{%0,%1,%2,%3},{%4,%5,%6,%7},{%8,%9},{%0,%1,%2,%3};"                     \
        : "+f"((c)[0]), "+f"((c)[1]), "+f"((c)[2]), "+f"((c)[3])                 \
        : "r"((a)[0]), "r"((a)[1]), "r"((a)[2]), "r"((a)[3]),                    \
          "r"((b)[0]), "r"((b)[1]))

#define LDSM_X4(r0, r1, r2, r3, addr)                                            \
    asm volatile("ldmatrix.sync.aligned.m8n8.x4.shared.b16 {%0,%1,%2,%3}, [%4];" \
                 : "=r"(r0), "=r"(r1), "=r"(r2), "=r"(r3) : "r"(addr))

__device__ __forceinline__ float qreduce(float v) {
    v += __shfl_xor_sync(0xffffffffu, v, 1);
    v += __shfl_xor_sync(0xffffffffu, v, 2);
    return v;
}

// MODE 1: A fp32 (convert to fp16), 4-head fused scores.
// MODE 2: A pre-fp16 (plain copy), 1-head fused scores.
template <int BN, int MODE>
__device__ void gemm_tc_dev(const float* __restrict__ A,
                            const __half* __restrict__ Ah,
                            const __half* __restrict__ Wh,
                            __half* __restrict__ Ch, int M,
                            const float* __restrict__ a_src,
                            const float* __restrict__ a_dst,
                            float* __restrict__ ss, float* __restrict__ sd) {
    constexpr int WM = 32, MT = 2;
    constexpr int WN = BN / 2;
    constexpr int NT = WN / 8;
    constexpr int PAD = 40;

    __shared__ __align__(16) __half sA[128][PAD];
    __shared__ __align__(16) __half sB[BN][PAD];
    __shared__ float sred_s[MODE == 2 ? 128 : 1][2];
    __shared__ float sred_d[MODE == 2 ? 128 : 1][2];

    const int tid = threadIdx.x;
    const int wid = tid >> 5, lane = tid & 31;
    const int row0 = blockIdx.x * 128;
    const int wm = wid >> 1, wn = wid & 1;

    const int a_row = (lane & 7) + ((lane >> 3) & 1) * 8;
    const int a_col = (lane >> 4) * 8;
    const int b_n   = (lane & 7) + ((lane >> 4) & 1) * 8;
    const int b_k   = ((lane >> 3) & 1) * 8;

    const unsigned uA = (unsigned)__cvta_generic_to_shared(&sA[0][0]);
    const unsigned uB = (unsigned)__cvta_generic_to_shared(&sB[0][0]);

    float acc[MT][NT][4] = {};

    for (int kt = 0; kt < 128; kt += 32) {
#pragma unroll
        for (int i = 0; i < 4; i++) {
            int f4 = tid + i * 256;
            int r = f4 >> 3, c4 = (f4 & 7) * 4;
            if (MODE == 1) {
                float4 v = make_float4(0.f, 0.f, 0.f, 0.f);
                if (row0 + r < M)
                    v = *(const float4*)(A + (size_t)(row0 + r) * 128 + kt + c4);
                __half2 h01 = __floats2half2_rn(v.x, v.y);
                __half2 h23 = __floats2half2_rn(v.z, v.w);
                *(uint2*)&sA[r][c4] =
                    make_uint2(*(unsigned*)&h01, *(unsigned*)&h23);
            } else {
                uint2 h = make_uint2(0u, 0u);
                if (row0 + r < M)
                    h = *(const uint2*)(Ah + (size_t)(row0 + r) * 128 + kt + c4);
                *(uint2*)&sA[r][c4] = h;
            }
        }
#pragma unroll
        for (int i = 0; i < BN / 32; i++) {
            int u = tid + i * 256;
            int n = u >> 3, c4 = (u & 7) * 4;
            *(uint2*)&sB[n][c4] = *(const uint2*)(Wh + n * 128 + kt + c4);
        }
        __syncthreads();

#pragma unroll
        for (int ks = 0; ks < 32; ks += 16) {
            unsigned a[MT][4], b[NT][2];
#pragma unroll
            for (int mi = 0; mi < MT; mi++) {
                unsigned off =
                    (unsigned)((wm * WM + mi * 16 + a_row) * PAD + ks + a_col) * 2u;
                LDSM_X4(a[mi][0], a[mi][1], a[mi][2], a[mi][3], uA + off);
            }
#pragma unroll
            for (int np = 0; np < NT; np += 2) {
                unsigned off =
                    (unsigned)((wn * WN + np * 8 + b_n) * PAD + ks + b_k) * 2u;
                LDSM_X4(b[np][0], b[np][1], b[np + 1][0], b[np + 1][1], uB + off);
            }
#pragma unroll
            for (int mi = 0; mi < MT; mi++)
#pragma unroll
                for (int ni = 0; ni < NT; ni++) MMA_F16(acc[mi][ni], a[mi], b[ni]);
        }
        __syncthreads();
    }

    // ---- write C as fp16 (gather-only consumer)
#pragma unroll
    for (int mi = 0; mi < MT; mi++) {
#pragma unroll
        for (int ni = 0; ni < NT; ni++) {
            int r = row0 + wm * WM + mi * 16 + (lane >> 2);
            int c = wn * WN + ni * 8 + (lane & 3) * 2;
            if (r < M)
                *(__half2*)(Ch + (size_t)r * BN + c) =
                    __floats2half2_rn(acc[mi][ni][0], acc[mi][ni][1]);
            if (r + 8 < M)
                *(__half2*)(Ch + (size_t)(r + 8) * BN + c) =
                    __floats2half2_rn(acc[mi][ni][2], acc[mi][ni][3]);
        }
    }

    // ---- fused attention scores
    if (MODE == 1) {
        float ps[MT][2][2] = {}, pd[MT][2][2] = {};
#pragma unroll
        for (int ni = 0; ni < NT; ni++) {
            int c = wn * WN + ni * 8 + (lane & 3) * 2;
            float a0 = a_src[c], a1 = a_src[c + 1];
            float d0 = a_dst[c], d1 = a_dst[c + 1];
            int hb = ni >> 2;
#pragma unroll
            for (int mi = 0; mi < MT; mi++) {
                ps[mi][0][hb] += acc[mi][ni][0] * a0 + acc[mi][ni][1] * a1;
                ps[mi][1][hb] += acc[mi][ni][2] * a0 + acc[mi][ni][3] * a1;
                pd[mi][0][hb] += acc[mi][ni][0] * d0 + acc[mi][ni][1] * d1;
                pd[mi][1][hb] += acc[mi][ni][2] * d0 + acc[mi][ni][3] * d1;
            }
        }
#pragma unroll
        for (int mi = 0; mi < MT; mi++)
#pragma unroll
            for (int rh = 0; rh < 2; rh++)
#pragma unroll
                for (int hb = 0; hb < 2; hb++) {
                    float vs = qreduce(ps[mi][rh][hb]);
                    float vd = qreduce(pd[mi][rh][hb]);
                    if ((lane & 3) == 0) {
                        int r = row0 + wm * WM + mi * 16 + (lane >> 2) + rh * 8;
                        if (r < M) {
                            int head = wn * 2 + hb;
                            ss[(size_t)r * 4 + head] = vs;
                            sd[(size_t)r * 4 + head] = vd;
                        }
                    }
                }
    } else if (MODE == 2) {
        float ps[MT][2] = {}, pd[MT][2] = {};
#pragma unroll
        for (int ni = 0; ni < NT; ni++) {
            int c = wn * WN + ni * 8 + (lane & 3) * 2;
            float a0 = a_src[c], a1 = a_src[c + 1];
            float d0 = a_dst[c], d1 = a_dst[c + 1];
#pragma unroll
            for (int mi = 0; mi < MT; mi++) {
                ps[mi][0] += acc[mi][ni][0] * a0 + acc[mi][ni][1] * a1;
                ps[mi][1] += acc[mi][ni][2] * a0 + acc[mi][ni][3] * a1;
                pd[mi][0] += acc[mi][ni][0] * d0 + acc[mi][ni][1] * d1;
                pd[mi][1] += acc[mi][ni][2] * d0 + acc[mi][ni][3] * d1;
            }
        }
#pragma unroll
        for (int mi = 0; mi < MT; mi++)
#pragma unroll
            for (int rh = 0; rh < 2; rh++) {
                float vs = qreduce(ps[mi][rh]);
                float vd = qreduce(pd[mi][rh]);
                if ((lane & 3) == 0) {
                    int rl = wm * WM + mi * 16 + (lane >> 2) + rh * 8;
                    sred_s[rl][wn] = vs;
                    sred_d[rl][wn] = vd;
                }
            }
        __syncthreads();
        if (tid < 128) {
            int r = row0 + tid;
            if (r < M) {
                ss[r] = sred_s[tid][0] + sred_s[tid][1];
                sd[r] = sred_d[tid][0] + sred_d[tid][1];
            }
        }
    }
}

__global__ void __launch_bounds__(256, 2)
gemm1_tc_kernel(const float* __restrict__ x, const float* __restrict__ as1,
                const float* __restrict__ ad1) {
    gemm_tc_dev<128, 1>(x, nullptr, g_W1h, g_h1h, N_NODES, as1, ad1, g_ss1, g_sd1);
}

__global__ void __launch_bounds__(256, 2)
gemm2_tc_kernel(const float* __restrict__ as2, const float* __restrict__ ad2) {
    gemm_tc_dev<64, 2>(nullptr, g_O1h, g_W2h, g_h2h, N_NODES, as2, ad2, g_ss2, g_sd2);
}

// ---------------- aggregation layer 1 (single-pass, unroll-8 gather) ----------
__global__ void __launch_bounds__(256)
agg1_kernel(const float* __restrict__ bias) {
    const int w = threadIdx.x >> 5;
    const int lane = threadIdx.x & 31;
    const int n = blockIdx.x * 8 + w;

    __shared__ int   sm_s[8][32];
    __shared__ float sm_a[8][32][4];

    if (n >= N_NODES) return;
    const int beg = g_off[n];
    const int deg = g_off[n + 1] - beg;

    const float4 sdv = *(const float4*)(g_sd1 + n * 4);
    const int head = lane >> 3;
    float4 acc = make_float4(0.f, 0.f, 0.f, 0.f);
    float den = 0.f;
    const __half* __restrict__ h1 = g_h1h;

    for (int j0 = 0; j0 < deg; j0 += 32) {
        int cnt = min(32, deg - j0);
        if (lane < cnt) {
            int s = g_esrc[beg + j0 + lane];
            float4 ss = *(const float4*)(g_ss1 + s * 4);
            sm_s[w][lane] = s;
            sm_a[w][lane][0] = __expf(lrelu(ss.x + sdv.x));
            sm_a[w][lane][1] = __expf(lrelu(ss.y + sdv.y));
            sm_a[w][lane][2] = __expf(lrelu(ss.z + sdv.z));
            sm_a[w][lane][3] = __expf(lrelu(ss.w + sdv.w));
        }
        __syncwarp();
        int j = 0;
        for (; j + 8 <= cnt; j += 8) {
            int   sj[8];
            float aj[8];
            uint2 uj[8];
#pragma unroll
            for (int q = 0; q < 8; q++) {
                sj[q] = sm_s[w][j + q];
                aj[q] = sm_a[w][j + q][head];
            }
#pragma unroll
            for (int q = 0; q < 8; q++)
                uj[q] = *(const uint2*)&h1[(size_t)sj[q] * 128 + lane * 4];
#pragma unroll
            for (int q = 0; q < 8; q++) {
                den += aj[q];
                float2 f;
                f = __half22float2(*(__half2*)&uj[q].x);
                acc.x = fmaf(aj[q], f.x, acc.x); acc.y = fmaf(aj[q], f.y, acc.y);
                f = __half22float2(*(__half2*)&uj[q].y);
                acc.z = fmaf(aj[q], f.x, acc.z); acc.w = fmaf(aj[q], f.y, acc.w);
            }
        }
        for (; j < cnt; j++) {
            int s0 = sm_s[w][j];
            float a0 = sm_a[w][j][head];
            uint2 u0 = *(const uint2*)&h1[(size_t)s0 * 128 + lane * 4];
            den += a0;
            float2 f;
            f = __half22float2(*(__half2*)&u0.x);
            acc.x = fmaf(a0, f.x, acc.x); acc.y = fmaf(a0, f.y, acc.y);
            f = __half22float2(*(__half2*)&u0.y);
            acc.z = fmaf(a0, f.x, acc.z); acc.w = fmaf(a0, f.y, acc.w);
        }
        __syncwarp();
    }
    const float inv = 1.f / den;
    float4 b = *(const float4*)&bias[lane * 4];
    float rx = fmaxf(fmaf(acc.x, inv, b.x), 0.f);
    float ry = fmaxf(fmaf(acc.y, inv, b.y), 0.f);
    float rz = fmaxf(fmaf(acc.z, inv, b.z), 0.f);
    float rw = fmaxf(fmaf(acc.w, inv, b.w), 0.f);
    __half2 h01 = __floats2half2_rn(rx, ry);
    __half2 h23 = __floats2half2_rn(rz, rw);
    *(uint2*)&g_O1h[(size_t)n * 128 + lane * 4] =
        make_uint2(*(unsigned*)&h01, *(unsigned*)&h23);
}

// ---------------- aggregation layer 2 (single-pass, unroll-8 gather) ----------
__global__ void __launch_bounds__(256)
agg2_kernel(const float* __restrict__ bias, float* __restrict__ out) {
    const int w = threadIdx.x >> 5;
    const int lane = threadIdx.x & 31;
    const int n = blockIdx.x * 8 + w;

    __shared__ int   sm_s[8][32];
    __shared__ float sm_a[8][32];

    if (n >= N_NODES) return;
    const int beg = g_off[n];
    const int deg = g_off[n + 1] - beg;

    const float sd = g_sd2[n];
    float ax = 0.f, ay = 0.f, den = 0.f;
    const __half* __restrict__ h2 = g_h2h;

    for (int j0 = 0; j0 < deg; j0 += 32) {
        int cnt = min(32, deg - j0);
        if (lane < cnt) {
            int s = g_esrc[beg + j0 + lane];
            sm_s[w][lane] = s;
            sm_a[w][lane] = __expf(lrelu(g_ss2[s] + sd));
        }
        __syncwarp();
        int j = 0;
        for (; j + 8 <= cnt; j += 8) {
            int     sj[8];
            float   aj[8];
            __half2 vj[8];
#pragma unroll
            for (int q = 0; q < 8; q++) {
                sj[q] = sm_s[w][j + q];
                aj[q] = sm_a[w][j + q];
            }
#pragma unroll
            for (int q = 0; q < 8; q++)
                vj[q] = *(const __half2*)&h2[(size_t)sj[q] * 64 + lane * 2];
#pragma unroll
            for (int q = 0; q < 8; q++) {
                den += aj[q];
                float2 f = __half22float2(vj[q]);
                ax = fmaf(aj[q], f.x, ax);
                ay = fmaf(aj[q], f.y, ay);
            }
        }
        for (; j < cnt; j++) {
            int s0 = sm_s[w][j];
            float a0 = sm_a[w][j];
            __half2 v0 = *(const __half2*)&h2[(size_t)s0 * 64 + lane * 2];
            den += a0;
            float2 f = __half22float2(v0);
            ax = fmaf(a0, f.x, ax); ay = fmaf(a0, f.y, ay);
        }
        __syncwarp();
    }
    const float inv = 1.f / den;
    float2 b = *(const float2*)&bias[lane * 2];
    float2 r = make_float2(fmaf(ax, inv, b.x), fmaf(ay, inv, b.y));
    *(float2*)&out[(size_t)n * 64 + lane * 2] = r;
}

// ---------------- launch ----------------
extern "C" void kernel_launch(void* const* d_in, const int* in_sizes, int n_in,
                              void* d_out, int out_size) {
    const float* x   = (const float*)d_in[0];
    const int*   ei  = (const int*)d_in[1];
    const float* W1  = (const float*)d_in[2];
    const float* as1 = (const float*)d_in[3];
    const float* ad1 = (const float*)d_in[4];
    const float* b1  = (const float*)d_in[5];
    const float* W2  = (const float*)d_in[6];
    const float* as2 = (const float*)d_in[7];
    const float* ad2 = (const float*)d_in[8];
    const float* b2  = (const float*)d_in[9];
    float* out = (float*)d_out;

    static cudaStream_t s2 = nullptr;
    static cudaEvent_t evFork = nullptr, evJoin = nullptr;
    if (!s2) {
        cudaStreamCreateWithFlags(&s2, cudaStreamNonBlocking);
        cudaEventCreateWithFlags(&evFork, cudaEventDisableTiming);
        cudaEventCreateWithFlags(&evJoin, cudaEventDisableTiming);
    }

    const int NCH = (N_NODES / 4 + 1023) / 1024;  // 13 chunks of 4096 nodes

    cudaEventRecord(evFork, 0);
    cudaStreamWaitEvent(s2, evFork, 0);

    init_deg_kernel<<<(N_NODES + 255) / 256, 256, 0, s2>>>();            // 1
    hist_kernel<<<(N_EDGES / 4 + 255) / 256, 256, 0, s2>>>(ei);          // 2
    convert_w_kernel<<<96, 256>>>(W1, W2);                               // 3 (main)
    gemm1_tc_kernel<<<(N_NODES + 127) / 128, 256>>>(x, as1, ad1);        // 4 (main)
    scan1_kernel<<<NCH, 1024, 0, s2>>>();                                // 5
    scan3_kernel<<<(N_NODES + 255) / 256, 256, 0, s2>>>(NCH);            // 6
    scatter_kernel<<<(N_EDGES / 4 + 255) / 256, 256, 0, s2>>>(ei);       // 7
    cudaEventRecord(evJoin, s2);

    cudaStreamWaitEvent(0, evJoin, 0);

    agg1_kernel<<<(N_NODES + 7) / 8, 256>>>(b1);
    gemm2_tc_kernel<<<(N_NODES + 127) / 128, 256>>>(as2, ad2);
    agg2_kernel<<<(N_NODES + 7) / 8, 256>>>(b2, out);
}